// round 11
// baseline (speedup 1.0000x reference)
#include <cuda_runtime.h>
#include <cuda_bf16.h>
#include <math.h>

#define NMAX 400000
typedef unsigned int uint32;

__device__ int g_cnt_m;
__device__ int g_cnt_u;
__device__ int g_mask_mode;
__device__ int g_idx[NMAX];

#define P_TGT_SP 0
#define P_TGT_TP 1572864
#define P_BG_SP  2359296
#define P_BG_TP  3932160
#define P_TOTAL  4718592
__device__ uint32 g_planes[P_TOTAL];

#define IMG_ST       0
#define IMG_BGST     8192
#define IMG_POSW1    16384
#define IMG_BGPOSW1  49152
#define IMG_ROTW1    81920
#define IMG_SHSW1    114688
#define IMG_POSW2    147456
#define IMG_ROTW2    148480
#define IMG_SHSW2    149504
#define IMG_BGPOSW2  155648
#define IMG_TOTAL    156672
__device__ uint32 g_wimg[IMG_TOTAL];

// ---------------- smem layout (u32 words) ----------------
#define SF_U   0          // feat: 128 x 32 words (16KB)
#define SA_U   4096       // h: 128 x 128 words (64KB)
#define SB_U   20480      // weight bufs 2 x 16384 words (2 x 64KB); buf0 doubles as h1
#define TOTAL_U 53248
#define SMEM_BYTES (TOTAL_U*4)
#define H1_OFF SB_U

static __device__ __forceinline__ float sigm(float x){ return 1.0f/(1.0f+expf(-x)); }
static __device__ __forceinline__ uint32 bpack(float a, float b){
    __nv_bfloat162 h = __float22bfloat162_rn(make_float2(a,b));
    return *reinterpret_cast<uint32*>(&h);
}
static __device__ __forceinline__ float2 bf2f(uint32 w){
    __nv_bfloat162 h; *reinterpret_cast<uint32*>(&h) = w;
    return __bfloat1622float2(h);
}
static __device__ __forceinline__ void ldsm4(uint32* r, uint32 addr){
    asm volatile("ldmatrix.sync.aligned.m8n8.x4.shared.b16 {%0,%1,%2,%3},[%4];"
      : "=r"(r[0]),"=r"(r[1]),"=r"(r[2]),"=r"(r[3]) : "r"(addr));
}
static __device__ __forceinline__ void mma16(float* d, const uint32* a, uint32 b0, uint32 b1){
    asm volatile("mma.sync.aligned.m16n8k16.row.col.f32.bf16.bf16.f32 "
      "{%0,%1,%2,%3},{%4,%5,%6,%7},{%8,%9},{%0,%1,%2,%3};"
      : "+f"(d[0]),"+f"(d[1]),"+f"(d[2]),"+f"(d[3])
      : "r"(a[0]),"r"(a[1]),"r"(a[2]),"r"(a[3]),"r"(b0),"r"(b1));
}
static __device__ __forceinline__ void cpa16(uint32 saddr, const void* g){
    asm volatile("cp.async.cg.shared.global [%0],[%1],16;" :: "r"(saddr), "l"(g));
}
static __device__ __forceinline__ void cp_commit(){ asm volatile("cp.async.commit_group;"); }
template<int N> static __device__ __forceinline__ void cp_wait(){ asm volatile("cp.async.wait_group %0;"::"n"(N)); }

// ---------------- converts (proven) ----------------
__global__ void convert_planes(const float* __restrict__ tsp, const float* __restrict__ ttp,
                               const float* __restrict__ bsp, const float* __restrict__ btp){
    int i = blockIdx.x*blockDim.x + threadIdx.x;
    if (i >= P_TOTAL) return;
    const float* src; int off;
    if      (i < P_TGT_TP){ src = tsp; off = i; }
    else if (i < P_BG_SP) { src = ttp; off = i - P_TGT_TP; }
    else if (i < P_BG_TP) { src = bsp; off = i - P_BG_SP; }
    else                  { src = btp; off = i - P_BG_TP; }
    g_planes[i] = bpack(src[2*off], src[2*off+1]);
}

__global__ void convert_kernel(const float* st_w, const float* bg_st_w,
    const float* pos_w1, const float* bgpos_w1, const float* rot_w1, const float* shs_w1,
    const float* pos_w2, const float* rot_w2, const float* shs_w2, const float* bgpos_w2)
{
    int i = blockIdx.x*blockDim.x + threadIdx.x;
    if (i >= IMG_TOTAL) return;
    if (i < IMG_POSW2){
        const float* src; int base;
        if      (i < IMG_BGST)   { src=st_w;    base=IMG_ST; }
        else if (i < IMG_POSW1)  { src=bg_st_w; base=IMG_BGST; }
        else if (i < IMG_BGPOSW1){ src=pos_w1;  base=IMG_POSW1; }
        else if (i < IMG_ROTW1)  { src=bgpos_w1;base=IMG_BGPOSW1; }
        else if (i < IMG_SHSW1)  { src=rot_w1;  base=IMG_ROTW1; }
        else                     { src=shs_w1;  base=IMG_SHSW1; }
        int wi = i - base;
        int wpc = 256*32;
        int chunk = wi / wpc, r = wi % wpc;
        int nrow = r >> 5, pw = r & 31;
        int q = (pw>>2) ^ (nrow&7);
        int p = (q<<2) | (pw&3);
        int k = chunk*64 + 2*p;
        g_wimg[i] = bpack(src[(size_t)k*256 + nrow], src[(size_t)(k+1)*256 + nrow]);
    } else {
        const float* src; int N, NT, base;
        if      (i < IMG_ROTW2)  { src=pos_w2;  N=3;  NT=1; base=IMG_POSW2; }
        else if (i < IMG_SHSW2)  { src=rot_w2;  N=4;  NT=1; base=IMG_ROTW2; }
        else if (i < IMG_BGPOSW2){ src=shs_w2;  N=48; NT=6; base=IMG_SHSW2; }
        else                     { src=bgpos_w2;N=3;  NT=1; base=IMG_BGPOSW2; }
        int wi = i - base;
        int lane = wi & 31;
        int tmp = wi >> 5;
        int h = tmp & 1;
        int tmp2 = tmp >> 1;
        int nt = tmp2 % NT;
        int kc = tmp2 / NT;
        int g = lane >> 2, tig = lane & 3;
        int k0 = kc*16 + 2*tig + 8*h;
        int col = nt*8 + g;
        float lo = 0.0f, hi = 0.0f;
        if (col < N){ lo = src[(size_t)k0*N + col]; hi = src[(size_t)(k0+1)*N + col]; }
        g_wimg[i] = bpack(lo, hi);
    }
}

// ---------------- setup + elem (proven) ----------------
__global__ void setup_kernel(const unsigned char* __restrict__ mb){
    __shared__ int s3f, s3f1, s1off;
    if (threadIdx.x == 0){ s3f = 0; s3f1 = 0; s1off = 0; }
    __syncthreads();
    int a = 0, b = 0, c = 0;
    for (int i = threadIdx.x; i < 4096; i += blockDim.x){
        unsigned v = mb[i];
        if (v == 0x3fu){ a = 1; if ((i & 3) == 1) b = 1; }
        if (v == 0x01u && (i & 3) != 0) c = 1;
    }
    if (a) atomicOr(&s3f, 1);
    if (b) atomicOr(&s3f1, 1);
    if (c) atomicOr(&s1off, 1);
    __syncthreads();
    if (threadIdx.x == 0){
        g_mask_mode = s3f ? (s3f1 ? 3 : 2) : (s1off ? 0 : 1);
        g_cnt_m = 0; g_cnt_u = 0;
    }
}
static __device__ __forceinline__ bool read_mask(const void* m, int i, int mode){
    if (mode == 0) return ((const unsigned char*)m)[i] != 0;
    if (mode == 1) return ((const int*)m)[i] != 0;
    if (mode == 2) return ((const float*)m)[i] != 0.0f;
    return ((const unsigned short*)m)[i] != 0;
}
__global__ void elem_kernel(const float* __restrict__ rot_emb, const float* __restrict__ shs_emb,
                            const float* __restrict__ tim, const float* __restrict__ h_emb,
                            const void* __restrict__ mask, float* __restrict__ out, int n){
    __shared__ int sm_m, sm_u, base_m, base_u;
    if (threadIdx.x == 0){ sm_m = 0; sm_u = 0; }
    __syncthreads();
    int i = blockIdx.x*blockDim.x + threadIdx.x;
    bool valid = (i < n);
    int mode = g_mask_mode;
    bool msk = false; int pos = 0;
    if (valid){
        msk = read_mask(mask, i, mode);
        pos = msk ? atomicAdd(&sm_m, 1) : atomicAdd(&sm_u, 1);
    }
    __syncthreads();
    if (threadIdx.x == 0){ base_m = atomicAdd(&g_cnt_m, sm_m); base_u = atomicAdd(&g_cnt_u, sm_u); }
    __syncthreads();
    if (!valid) return;
    float t0 = tim[0];
    float he0 = h_emb[3*i], he1 = h_emb[3*i+1], he2 = h_emb[3*i+2];
    float op;
    if (msk){ float mu = sigm(he2); float w = he1*he1; float d = t0 - mu; op = expf(-w*d*d); }
    else op = sigm(he0);
    out[(size_t)7*n + i] = op;
    if (msk){ g_idx[base_m + pos] = i; }
    else {
        g_idx[n - 1 - (base_u + pos)] = i;
        ((float4*)(out + (size_t)3*n))[i] = ((const float4*)rot_emb)[i];
        const float4* s4 = (const float4*)shs_emb + (size_t)i*12;
        float4* d4 = (float4*)(out + (size_t)8*n) + (size_t)i*12;
        #pragma unroll
        for (int q = 0; q < 12; q++) d4[q] = s4[q];
    }
}

// ---------------- staging ----------------
// 64KB (one K=128 macro-chunk = two contiguous image chunks)
static __device__ __forceinline__ void stage64(uint32 smem_base, int buf, const uint32* img, int cb){
    const int t = threadIdx.x;
    uint32 dst = smem_base + (SB_U + buf*16384 + t*32)*4;
    const uint32* s = img + cb*16384 + t*32;
    #pragma unroll
    for (int j = 0; j < 8; j++) cpa16(dst + j*16, s + j*4);
    cp_commit();
}
// 32KB (stem K=64)
static __device__ __forceinline__ void stage32(uint32 smem_base, int buf, const uint32* img){
    const int t = threadIdx.x;
    uint32 dst = smem_base + (SB_U + buf*16384 + t*16)*4;
    const uint32* s = img + t*16;
    #pragma unroll
    for (int j = 0; j < 4; j++) cpa16(dst + j*16, s + j*4);
    cp_commit();
}

// ---------------- MMA block: KS k-steps (k16 each) from one buffer ----------------
template<int KS>
static __device__ __forceinline__ void mma_block(
    float acc[2][8][4], uint32 bufByte, uint32 aBaseByte, int rowBytes, int qA0)
{
    const int t = threadIdx.x;
    const int lane = t & 31, w = t >> 5;
    const int wm = w >> 2, wn = w & 3;
    const int mb = wm*32, nb = wn*64;
    const int l7 = lane & 7, lm = lane >> 3;
    const int a_rl = l7 + ((lm & 1) << 3);
    const int a_qo = lm >> 1;
    const int b_kh = lm & 1;
    const int b_no = (lm >> 1) << 3;
    const int b_r7 = (b_no + l7) & 7;
    const uint32 Ab0 = aBaseByte + (uint32)(mb + a_rl) * rowBytes;
    const uint32 Ab1 = Ab0 + 16u * rowBytes;
    const uint32 Bthread = (uint32)(nb + b_no + l7) * 128u;
    #pragma unroll
    for (int ks = 0; ks < KS; ks++){
        uint32 sBcur = bufByte + (uint32)((ks >> 2) * 32768);
        int ksl = ks & 3;
        uint32 ar[2][4];
        int qA = qA0 + ks*2 + a_qo;
        uint32 axor = (uint32)((qA ^ l7) << 4);
        ldsm4(ar[0], Ab0 + axor);
        ldsm4(ar[1], Ab1 + axor);
        uint32 bxor = (uint32)(((ksl*2 + b_kh) ^ b_r7) << 4);
        #pragma unroll
        for (int j = 0; j < 4; j++){
            uint32 br[4];
            ldsm4(br, sBcur + Bthread + (uint32)(j*16*128) + bxor);
            #pragma unroll
            for (int mt = 0; mt < 2; mt++){
                mma16(acc[mt][2*j],     ar[mt], br[0], br[1]);
                mma16(acc[mt][2*j + 1], ar[mt], br[2], br[3]);
            }
        }
    }
}

static __device__ __forceinline__ void acc_zero(float acc[2][8][4]){
    #pragma unroll
    for (int mt = 0; mt < 2; mt++)
        #pragma unroll
        for (int nt = 0; nt < 8; nt++)
            #pragma unroll
            for (int i = 0; i < 4; i++) acc[mt][nt][i] = 0.0f;
}

// epilogue: acc -> bf16 canonical (bias + relu), dst row stride 128 words
static __device__ __forceinline__ void epi_big(
    float acc[2][8][4], const float* __restrict__ gb, uint32* __restrict__ dstU)
{
    const int t = threadIdx.x;
    const int lane = t & 31, w = t >> 5;
    const int wm = w >> 2, wn = w & 3;
    const int mb = wm*32, nb = wn*64;
    const int g = lane >> 2, tig = lane & 3;
    #pragma unroll
    for (int mt = 0; mt < 2; mt++){
        int r0 = mb + mt*16 + g, r1 = r0 + 8;
        #pragma unroll
        for (int nt = 0; nt < 8; nt++){
            int col = nb + nt*8 + 2*tig;
            float b0 = gb[col], b1 = gb[col+1];
            uint32 w0 = bpack(fmaxf(acc[mt][nt][0] + b0, 0.0f), fmaxf(acc[mt][nt][1] + b1, 0.0f));
            uint32 w1 = bpack(fmaxf(acc[mt][nt][2] + b0, 0.0f), fmaxf(acc[mt][nt][3] + b1, 0.0f));
            int p = wn*32 + nt*4 + tig;
            int phys = (((p>>2) ^ (g & 7)) << 2) | (p & 3);
            dstU[r0*128 + phys] = w0;
            dstU[r1*128 + phys] = w1;
        }
    }
}

// ---------------- w2 GEMMs: warps 0..7, A = h1 at H1_OFF (buf0), B frags direct from L2 ----------------
static __device__ __forceinline__ void gemm_w2_n8(float acc8[4], uint32 smem_base, const uint32* __restrict__ wp){
    const int t = threadIdx.x;
    const int lane = t & 31, w = (t >> 5) & 7;
    const int l7 = lane & 7, lm = lane >> 3;
    const int a_rl = l7 + ((lm & 1) << 3);
    const int a_qo = lm >> 1;
    #pragma unroll
    for (int i = 0; i < 4; i++) acc8[i] = 0.0f;
    const uint32 Ab = smem_base + H1_OFF*4 + (uint32)(w*16 + a_rl)*512u;
    #pragma unroll
    for (int kc = 0; kc < 16; kc++){
        uint32 ar[4];
        int qA = kc*2 + a_qo;
        ldsm4(ar, Ab + (uint32)((qA ^ l7) << 4));
        mma16(acc8, ar, wp[(kc*2)*32 + lane], wp[(kc*2+1)*32 + lane]);
    }
}
static __device__ __forceinline__ void gemm_w2_n48(float acc48[6][4], uint32 smem_base, const uint32* __restrict__ wp){
    const int t = threadIdx.x;
    const int lane = t & 31, w = (t >> 5) & 7;
    const int l7 = lane & 7, lm = lane >> 3;
    const int a_rl = l7 + ((lm & 1) << 3);
    const int a_qo = lm >> 1;
    #pragma unroll
    for (int nt = 0; nt < 6; nt++)
        #pragma unroll
        for (int i = 0; i < 4; i++) acc48[nt][i] = 0.0f;
    const uint32 Ab = smem_base + H1_OFF*4 + (uint32)(w*16 + a_rl)*512u;
    #pragma unroll 4
    for (int kc = 0; kc < 16; kc++){
        uint32 ar[4];
        int qA = kc*2 + a_qo;
        ldsm4(ar, Ab + (uint32)((qA ^ l7) << 4));
        #pragma unroll
        for (int nt = 0; nt < 6; nt++)
            mma16(acc48[nt], ar, wp[((kc*6+nt)*2)*32 + lane], wp[((kc*6+nt)*2+1)*32 + lane]);
    }
}

// ---------------- phase A (proven) ----------------
static __device__ __forceinline__ void phaseA(
    int seg, const float* __restrict__ rays, const float* __restrict__ tim,
    const int* sidx, uint32* __restrict__ sF)
{
    const int t = threadIdx.x;
    const int pt = t >> 2, fg = t & 3;
    const int gi = sidx[pt];
    float px = rays[3*gi], py = rays[3*gi+1], pz = rays[3*gi+2];
    float tv = tim[gi];
    float cx = fminf(fmaxf((px*(1.0f/1.3f) + 1.0f)*0.5f, 0.0f), 1.0f) * 127.0f;
    float cy = fminf(fmaxf((py*(1.0f/1.3f) + 1.0f)*0.5f, 0.0f), 1.0f) * 127.0f;
    float cz = fminf(fmaxf((pz*(1.0f/1.3f) + 1.0f)*0.5f, 0.0f), 1.0f) * 127.0f;
    float tq = fminf(fmaxf(tv, 0.0f), 1.0f) * 63.0f;

    const uint32* sp = g_planes + (seg ? P_BG_SP : P_TGT_SP);
    const uint32* tp = g_planes + (seg ? P_BG_TP : P_TGT_TP);

    const uint32* PB[6];
    int O00[6], O10[6], O01[6], O11[6];
    float W00[6], W10[6], W01[6], W11[6];
#define SETP(s, bp, R2, uu, vv) { \
    float u_ = fminf(fmaxf((uu), 0.0f), 127.0f); \
    float v_ = fminf(fmaxf((vv), 0.0f), (float)((R2)-1)); \
    int i0 = (int)u_; int j0 = (int)v_; \
    int i1 = min(i0+1, 127); int j1 = min(j0+1, (R2)-1); \
    float fu = u_ - (float)i0, fv = v_ - (float)j0; \
    PB[s] = (bp); \
    O00[s] = (i0*(R2)+j0)*32; O10[s] = (i1*(R2)+j0)*32; \
    O01[s] = (i0*(R2)+j1)*32; O11[s] = (i1*(R2)+j1)*32; \
    W00[s] = (1.0f-fu)*(1.0f-fv); W10[s] = fu*(1.0f-fv); \
    W01[s] = (1.0f-fu)*fv;        W11[s] = fu*fv; }
    SETP(0, sp,          128, cx, cy)
    SETP(1, sp + 524288, 128, cx, cz)
    SETP(2, sp + 1048576,128, cy, cz)
    SETP(3, tp,           64, cx, tq)
    SETP(4, tp + 262144,  64, cy, tq)
    SETP(5, tp + 524288,  64, cz, tq)
#undef SETP
    #pragma unroll
    for (int h = 0; h < 2; h++){
        int foff = fg*8 + h*4;
        float r[8];
        #pragma unroll
        for (int j = 0; j < 8; j++) r[j] = 1.0f;
        #pragma unroll
        for (int s = 0; s < 6; s++){
            const uint32* bp = PB[s] + foff;
            uint4 u00 = *(const uint4*)(bp + O00[s]);
            uint4 u10 = *(const uint4*)(bp + O10[s]);
            uint4 u01 = *(const uint4*)(bp + O01[s]);
            uint4 u11 = *(const uint4*)(bp + O11[s]);
            const uint32* a0 = (const uint32*)&u00;
            const uint32* a1 = (const uint32*)&u10;
            const uint32* a2 = (const uint32*)&u01;
            const uint32* a3 = (const uint32*)&u11;
            #pragma unroll
            for (int wd = 0; wd < 4; wd++){
                float2 c00 = bf2f(a0[wd]);
                float2 c10 = bf2f(a1[wd]);
                float2 c01 = bf2f(a2[wd]);
                float2 c11 = bf2f(a3[wd]);
                r[2*wd]   *= c00.x*W00[s] + c10.x*W10[s] + c01.x*W01[s] + c11.x*W11[s];
                r[2*wd+1] *= c00.y*W00[s] + c10.y*W10[s] + c01.y*W01[s] + c11.y*W11[s];
            }
        }
        #pragma unroll
        for (int j = 0; j < 4; j++){
            int p = foff + j;
            int phys = (((p>>2) ^ (pt & 7)) << 2) | (p & 3);
            sF[pt*32 + phys] = bpack(r[2*j], r[2*j+1]);
        }
    }
}

// ---------------- main kernel ----------------
__global__ void __launch_bounds__(512, 1) main_kernel(
    const float* __restrict__ rays, const float* __restrict__ rot_emb,
    const float* __restrict__ shs_emb, const float* __restrict__ tim,
    const float* __restrict__ st_b,   const float* __restrict__ bg_st_b,
    const float* __restrict__ pos_b1, const float* __restrict__ pos_b2,
    const float* __restrict__ bgpos_b1, const float* __restrict__ bgpos_b2,
    const float* __restrict__ rot_b1, const float* __restrict__ rot_b2,
    const float* __restrict__ shs_b1, const float* __restrict__ shs_b2,
    float* __restrict__ out, int n)
{
    extern __shared__ uint32 smu[];
    const uint32 smem_base = (uint32)__cvta_generic_to_shared(smu);
    __shared__ int sidx[128];
    __shared__ int s_meta[3];

    const int t = threadIdx.x;
    if (t == 0){
        int mc = g_cnt_m;
        int mtiles = (mc + 127) >> 7;
        int bid = blockIdx.x;
        int seg, start, cnt;
        if (bid < mtiles){ seg = 0; start = bid << 7; cnt = min(128, mc - start); }
        else {
            int uc = n - mc;
            start = (bid - mtiles) << 7;
            seg = 1;
            cnt = (start < uc) ? min(128, uc - start) : 0;
        }
        s_meta[0] = seg; s_meta[1] = cnt; s_meta[2] = start;
    }
    __syncthreads();
    const int cnt = s_meta[1];
    if (cnt <= 0) return;
    const int seg = s_meta[0], start = s_meta[2];
    if (t < 128){
        int j = (t < cnt) ? t : 0;
        sidx[t] = (seg == 0) ? g_idx[start + j] : g_idx[n - 1 - (start + j)];
    }
    __syncthreads();

    // prologue: stem (32KB) -> buf0; first head's c0 (64KB) -> buf1
    stage32(smem_base, 0, g_wimg + (seg ? IMG_BGST : IMG_ST));
    const uint32* h0img = g_wimg + (seg ? IMG_BGPOSW1 : IMG_POSW1);
    stage64(smem_base, 1, h0img, 0);

    phaseA(seg, rays, tim, sidx, smu + SF_U);

    float acc[2][8][4];
    const uint32 buf0 = smem_base + SB_U*4;
    const uint32 buf1 = smem_base + (SB_U + 16384)*4;

    // stem: A = feat (K=64) from buf0; head c0 may stay pending
    cp_wait<1>(); __syncthreads();
    acc_zero(acc);
    mma_block<4>(acc, buf0, smem_base + SF_U*4, 128, 0);
    __syncthreads();
    epi_big(acc, seg ? bg_st_b : st_b, smu + SA_U);
    __syncthreads();

    const int lane = t & 31, w = t >> 5;
    const int g = lane >> 2, tig = lane & 3;
    const int mb2 = (w & 7)*16;
    const uint32 sAByte = smem_base + SA_U*4;

    if (seg == 0){
        const uint32* w1imgs[3] = {g_wimg + IMG_POSW1, g_wimg + IMG_ROTW1, g_wimg + IMG_SHSW1};
        const float*  b1s[3]    = {pos_b1, rot_b1, shs_b1};
        #pragma unroll 1
        for (int hd = 0; hd < 3; hd++){
            // c1 -> buf0 (prev contents dead)
            stage64(smem_base, 0, w1imgs[hd], 1);
            cp_wait<1>(); __syncthreads();      // c0 (buf1) arrived
            acc_zero(acc);
            mma_block<8>(acc, buf1, sAByte, 512, 0);
            cp_wait<0>(); __syncthreads();      // c1 (buf0) arrived
            mma_block<8>(acc, buf0, sAByte, 512, 16);
            __syncthreads();                    // all reads of buf0 done
            epi_big(acc, b1s[hd], smu + H1_OFF);  // h1 -> buf0
            if (hd < 2) stage64(smem_base, 1, w1imgs[hd+1], 0);  // next c0 -> buf1
            __syncthreads();                    // h1 visible
            if (hd == 0){
                if (w < 8){
                    float a8[4];
                    gemm_w2_n8(a8, smem_base, g_wimg + IMG_POSW2);
                    #pragma unroll
                    for (int i = 0; i < 2; i++){
                        int gi = sidx[mb2 + g + 8*i];
                        #pragma unroll
                        for (int jj = 0; jj < 2; jj++){
                            int col = 2*tig + jj;
                            if (col < 3) out[(size_t)gi*3 + col] = rays[gi*3 + col] + a8[i*2+jj] + pos_b2[col];
                        }
                    }
                }
            } else if (hd == 1){
                if (w < 8){
                    float a8[4];
                    gemm_w2_n8(a8, smem_base, g_wimg + IMG_ROTW2);
                    #pragma unroll
                    for (int i = 0; i < 2; i++){
                        int gi = sidx[mb2 + g + 8*i];
                        #pragma unroll
                        for (int jj = 0; jj < 2; jj++){
                            int col = 2*tig + jj;
                            if (col < 4) out[(size_t)3*n + (size_t)gi*4 + col] = rot_emb[(size_t)gi*4 + col] + a8[i*2+jj] + rot_b2[col];
                        }
                    }
                }
            } else {
                if (w < 8){
                    float a48[6][4];
                    gemm_w2_n48(a48, smem_base, g_wimg + IMG_SHSW2);
                    float* o8 = out + (size_t)8*n;
                    #pragma unroll
                    for (int i = 0; i < 2; i++){
                        int gi = sidx[mb2 + g + 8*i];
                        const float* se = shs_emb + (size_t)gi*48;
                        float* od = o8 + (size_t)gi*48;
                        #pragma unroll
                        for (int nt = 0; nt < 6; nt++){
                            #pragma unroll
                            for (int jj = 0; jj < 2; jj++){
                                int col = nt*8 + 2*tig + jj;
                                od[col] = se[col] + a48[nt][i*2+jj] + shs_b2[col];
                            }
                        }
                    }
                }
            }
            if (hd < 2) __syncthreads();        // protect buf0 before next head's stage c1
        }
    } else {
        stage64(smem_base, 0, g_wimg + IMG_BGPOSW1, 1);
        cp_wait<1>(); __syncthreads();
        acc_zero(acc);
        mma_block<8>(acc, buf1, sAByte, 512, 0);
        cp_wait<0>(); __syncthreads();
        mma_block<8>(acc, buf0, sAByte, 512, 16);
        __syncthreads();
        epi_big(acc, bgpos_b1, smu + H1_OFF);
        __syncthreads();
        if (w < 8){
            float a8[4];
            gemm_w2_n8(a8, smem_base, g_wimg + IMG_BGPOSW2);
            #pragma unroll
            for (int i = 0; i < 2; i++){
                int gi = sidx[mb2 + g + 8*i];
                #pragma unroll
                for (int jj = 0; jj < 2; jj++){
                    int col = 2*tig + jj;
                    if (col < 3) out[(size_t)gi*3 + col] = rays[gi*3 + col] + a8[i*2+jj] + bgpos_b2[col];
                }
            }
        }
    }
}

extern "C" void kernel_launch(void* const* d_in, const int* in_sizes, int n_in,
                              void* d_out, int out_size) {
    const float* rays    = (const float*)d_in[0];
    const float* rot_emb = (const float*)d_in[1];
    const float* shs_emb = (const float*)d_in[3];
    const float* tim     = (const float*)d_in[5];
    const float* h_emb   = (const float*)d_in[6];
    const void*  mask    = d_in[7];
    const float* tgt_sp  = (const float*)d_in[8];
    const float* tgt_tp  = (const float*)d_in[9];
    const float* bg_sp   = (const float*)d_in[10];
    const float* bg_tp   = (const float*)d_in[11];
    const float* st_w    = (const float*)d_in[12];
    const float* st_b    = (const float*)d_in[13];
    const float* bg_st_w = (const float*)d_in[14];
    const float* bg_st_b = (const float*)d_in[15];
    const float* pos_w1  = (const float*)d_in[16];
    const float* pos_b1  = (const float*)d_in[17];
    const float* pos_w2  = (const float*)d_in[18];
    const float* pos_b2  = (const float*)d_in[19];
    const float* bgpos_w1= (const float*)d_in[20];
    const float* bgpos_b1= (const float*)d_in[21];
    const float* bgpos_w2= (const float*)d_in[22];
    const float* bgpos_b2= (const float*)d_in[23];
    const float* rot_w1  = (const float*)d_in[24];
    const float* rot_b1  = (const float*)d_in[25];
    const float* rot_w2  = (const float*)d_in[26];
    const float* rot_b2  = (const float*)d_in[27];
    const float* shs_w1  = (const float*)d_in[28];
    const float* shs_b1  = (const float*)d_in[29];
    const float* shs_w2  = (const float*)d_in[30];
    const float* shs_b2  = (const float*)d_in[31];
    float* out = (float*)d_out;
    int n = in_sizes[0] / 3;

    cudaFuncSetAttribute(main_kernel, cudaFuncAttributeMaxDynamicSharedMemorySize, SMEM_BYTES);

    convert_planes<<<(P_TOTAL + 255)/256, 256>>>(tgt_sp, tgt_tp, bg_sp, bg_tp);
    convert_kernel<<<(IMG_TOTAL + 255)/256, 256>>>(
        st_w, bg_st_w, pos_w1, bgpos_w1, rot_w1, shs_w1,
        pos_w2, rot_w2, shs_w2, bgpos_w2);
    setup_kernel<<<1, 256>>>((const unsigned char*)mask);
    elem_kernel<<<(n + 255)/256, 256>>>(rot_emb, shs_emb, tim, h_emb, mask, out, n);
    int nb = (n + 127)/128 + 1;
    main_kernel<<<nb, 512, SMEM_BYTES>>>(
        rays, rot_emb, shs_emb, tim,
        st_b, bg_st_b,
        pos_b1, pos_b2, bgpos_b1, bgpos_b2,
        rot_b1, rot_b2, shs_b1, shs_b2,
        out, n);
}

// round 12
// speedup vs baseline: 1.3112x; 1.3112x over previous
#include <cuda_runtime.h>
#include <cuda_bf16.h>
#include <math.h>

#define NMAX 400000
typedef unsigned int uint32;

__device__ int g_cnt_m;
__device__ int g_cnt_u;
__device__ int g_mask_mode;
__device__ int g_idx[NMAX];

#define P_TGT_SP 0
#define P_TGT_TP 1572864
#define P_BG_SP  2359296
#define P_BG_TP  3932160
#define P_TOTAL  4718592
__device__ uint32 g_planes[P_TOTAL];

#define IMG_ST       0
#define IMG_BGST     8192
#define IMG_POSW1    16384
#define IMG_BGPOSW1  49152
#define IMG_ROTW1    81920
#define IMG_SHSW1    114688
#define IMG_POSW2    147456
#define IMG_ROTW2    148480
#define IMG_SHSW2    149504
#define IMG_BGPOSW2  155648
#define IMG_TOTAL    156672
__device__ uint32 g_wimg[IMG_TOTAL];

// ---------------- smem layout (u32 words) ----------------
#define SF_U   0          // feat: 128 x 32 words
#define SA_U   4096       // h: 128 x 128 words
#define SB_U   20480      // weight bufs 3 x 8192 words; bufs 1-2 double as h1
#define TOTAL_U 45056
#define SMEM_BYTES (TOTAL_U*4)
#define H1_OFF (SB_U + 8192)

static __device__ __forceinline__ float sigm(float x){ return 1.0f/(1.0f+expf(-x)); }
static __device__ __forceinline__ uint32 bpack(float a, float b){
    __nv_bfloat162 h = __float22bfloat162_rn(make_float2(a,b));
    return *reinterpret_cast<uint32*>(&h);
}
static __device__ __forceinline__ float2 bf2f(uint32 w){
    __nv_bfloat162 h; *reinterpret_cast<uint32*>(&h) = w;
    return __bfloat1622float2(h);
}
static __device__ __forceinline__ void ldsm4(uint32* r, uint32 addr){
    asm volatile("ldmatrix.sync.aligned.m8n8.x4.shared.b16 {%0,%1,%2,%3},[%4];"
      : "=r"(r[0]),"=r"(r[1]),"=r"(r[2]),"=r"(r[3]) : "r"(addr));
}
static __device__ __forceinline__ void mma16(float* d, const uint32* a, uint32 b0, uint32 b1){
    asm volatile("mma.sync.aligned.m16n8k16.row.col.f32.bf16.bf16.f32 "
      "{%0,%1,%2,%3},{%4,%5,%6,%7},{%8,%9},{%0,%1,%2,%3};"
      : "+f"(d[0]),"+f"(d[1]),"+f"(d[2]),"+f"(d[3])
      : "r"(a[0]),"r"(a[1]),"r"(a[2]),"r"(a[3]),"r"(b0),"r"(b1));
}
static __device__ __forceinline__ void cpa16(uint32 saddr, const void* g){
    asm volatile("cp.async.cg.shared.global [%0],[%1],16;" :: "r"(saddr), "l"(g));
}
static __device__ __forceinline__ void cp_commit(){ asm volatile("cp.async.commit_group;"); }
template<int N> static __device__ __forceinline__ void cp_wait(){ asm volatile("cp.async.wait_group %0;"::"n"(N)); }

// ---------------- setup: mask dtype sniff + counter reset ----------------
__global__ void setup_kernel(const unsigned char* __restrict__ mb){
    __shared__ int s3f, s3f1, s1off;
    if (threadIdx.x == 0){ s3f = 0; s3f1 = 0; s1off = 0; }
    __syncthreads();
    int a = 0, b = 0, c = 0;
    for (int i = threadIdx.x; i < 4096; i += blockDim.x){
        unsigned v = mb[i];
        if (v == 0x3fu){ a = 1; if ((i & 3) == 1) b = 1; }
        if (v == 0x01u && (i & 3) != 0) c = 1;
    }
    if (a) atomicOr(&s3f, 1);
    if (b) atomicOr(&s3f1, 1);
    if (c) atomicOr(&s1off, 1);
    __syncthreads();
    if (threadIdx.x == 0){
        g_mask_mode = s3f ? (s3f1 ? 3 : 2) : (s1off ? 0 : 1);
        g_cnt_m = 0; g_cnt_u = 0;
    }
}
static __device__ __forceinline__ bool read_mask(const void* m, int i, int mode){
    if (mode == 0) return ((const unsigned char*)m)[i] != 0;
    if (mode == 1) return ((const int*)m)[i] != 0;
    if (mode == 2) return ((const float*)m)[i] != 0.0f;
    return ((const unsigned short*)m)[i] != 0;
}

// ---------------- merged prep kernel: plane convert + weight convert + elem ----------------
#define PB_BLKS 18432            /* P_TOTAL / 256 */
#define WB_BLKS 612              /* ceil(IMG_TOTAL / 256) */
__global__ void prep_kernel(
    const float* __restrict__ tsp, const float* __restrict__ ttp,
    const float* __restrict__ bsp, const float* __restrict__ btp,
    const float* st_w, const float* bg_st_w,
    const float* pos_w1, const float* bgpos_w1, const float* rot_w1, const float* shs_w1,
    const float* pos_w2, const float* rot_w2, const float* shs_w2, const float* bgpos_w2,
    const float* __restrict__ rot_emb, const float* __restrict__ shs_emb,
    const float* __restrict__ tim, const float* __restrict__ h_emb,
    const void* __restrict__ mask, float* __restrict__ out, int n)
{
    int bid = blockIdx.x;
    if (bid < PB_BLKS){
        // ---- plane convert ----
        int i = bid*256 + threadIdx.x;
        const float* src; int off;
        if      (i < P_TGT_TP){ src = tsp; off = i; }
        else if (i < P_BG_SP) { src = ttp; off = i - P_TGT_TP; }
        else if (i < P_BG_TP) { src = bsp; off = i - P_BG_SP; }
        else                  { src = btp; off = i - P_BG_TP; }
        g_planes[i] = bpack(src[2*off], src[2*off+1]);
        return;
    }
    bid -= PB_BLKS;
    if (bid < WB_BLKS){
        // ---- weight convert ----
        int i = bid*256 + threadIdx.x;
        if (i >= IMG_TOTAL) return;
        if (i < IMG_POSW2){
            const float* src; int base;
            if      (i < IMG_BGST)   { src=st_w;    base=IMG_ST; }
            else if (i < IMG_POSW1)  { src=bg_st_w; base=IMG_BGST; }
            else if (i < IMG_BGPOSW1){ src=pos_w1;  base=IMG_POSW1; }
            else if (i < IMG_ROTW1)  { src=bgpos_w1;base=IMG_BGPOSW1; }
            else if (i < IMG_SHSW1)  { src=rot_w1;  base=IMG_ROTW1; }
            else                     { src=shs_w1;  base=IMG_SHSW1; }
            int wi = i - base;
            int wpc = 256*32;
            int chunk = wi / wpc, r = wi % wpc;
            int nrow = r >> 5, pw = r & 31;
            int q = (pw>>2) ^ (nrow&7);
            int p = (q<<2) | (pw&3);
            int k = chunk*64 + 2*p;
            g_wimg[i] = bpack(src[(size_t)k*256 + nrow], src[(size_t)(k+1)*256 + nrow]);
        } else {
            const float* src; int N, NT, base;
            if      (i < IMG_ROTW2)  { src=pos_w2;  N=3;  NT=1; base=IMG_POSW2; }
            else if (i < IMG_SHSW2)  { src=rot_w2;  N=4;  NT=1; base=IMG_ROTW2; }
            else if (i < IMG_BGPOSW2){ src=shs_w2;  N=48; NT=6; base=IMG_SHSW2; }
            else                     { src=bgpos_w2;N=3;  NT=1; base=IMG_BGPOSW2; }
            int wi = i - base;
            int lane = wi & 31;
            int tmp = wi >> 5;
            int h = tmp & 1;
            int tmp2 = tmp >> 1;
            int nt = tmp2 % NT;
            int kc = tmp2 / NT;
            int g = lane >> 2, tig = lane & 3;
            int k0 = kc*16 + 2*tig + 8*h;
            int col = nt*8 + g;
            float lo = 0.0f, hi = 0.0f;
            if (col < N){ lo = src[(size_t)k0*N + col]; hi = src[(size_t)(k0+1)*N + col]; }
            g_wimg[i] = bpack(lo, hi);
        }
        return;
    }
    bid -= WB_BLKS;
    // ---- elem ----
    __shared__ int sm_m, sm_u, base_m, base_u;
    if (threadIdx.x == 0){ sm_m = 0; sm_u = 0; }
    __syncthreads();
    int i = bid*256 + threadIdx.x;
    bool valid = (i < n);
    int mode = g_mask_mode;
    bool msk = false; int pos = 0;
    if (valid){
        msk = read_mask(mask, i, mode);
        pos = msk ? atomicAdd(&sm_m, 1) : atomicAdd(&sm_u, 1);
    }
    __syncthreads();
    if (threadIdx.x == 0){ base_m = atomicAdd(&g_cnt_m, sm_m); base_u = atomicAdd(&g_cnt_u, sm_u); }
    __syncthreads();
    if (!valid) return;
    float t0 = tim[0];
    float he0 = h_emb[3*i], he1 = h_emb[3*i+1], he2 = h_emb[3*i+2];
    float op;
    if (msk){ float mu = sigm(he2); float w = he1*he1; float d = t0 - mu; op = expf(-w*d*d); }
    else op = sigm(he0);
    out[(size_t)7*n + i] = op;
    if (msk){ g_idx[base_m + pos] = i; }
    else {
        g_idx[n - 1 - (base_u + pos)] = i;
        ((float4*)(out + (size_t)3*n))[i] = ((const float4*)rot_emb)[i];
        const float4* s4 = (const float4*)shs_emb + (size_t)i*12;
        float4* d4 = (float4*)(out + (size_t)8*n) + (size_t)i*12;
        #pragma unroll
        for (int q = 0; q < 12; q++) d4[q] = s4[q];
    }
}

// ---------------- staging: 512 threads, 32KB chunk -> buf 0..2 ----------------
static __device__ __forceinline__ void stage_chunk(uint32 smem_base, int buf, const uint32* img, int chunk){
    const int t = threadIdx.x;
    uint32 dst = smem_base + (SB_U + buf*8192 + t*16)*4;
    const uint32* s = img + chunk*8192 + t*16;
    #pragma unroll
    for (int j = 0; j < 4; j++) cpa16(dst + j*16, s + j*4);
    cp_commit();
}

// ---------------- big GEMM: 128x256, 16 warps (4m x 4n), 3-buf rotation ----------------
template<int PEND>
static __device__ __forceinline__ void gemm_big3(
    float acc[2][8][4], const uint32* gimg, uint32 smem_base,
    uint32 aBaseByte, int rowBytes, int kchunks, int s0)
{
    const int t = threadIdx.x;
    const int lane = t & 31, w = t >> 5;
    const int wm = w >> 2, wn = w & 3;
    const int mb = wm*32, nb = wn*64;
    const int l7 = lane & 7, lm = lane >> 3;
    const int a_rl = l7 + ((lm & 1) << 3);
    const int a_qo = lm >> 1;
    const int b_kh = lm & 1;
    const int b_no = (lm >> 1) << 3;
    const int b_r7 = (b_no + l7) & 7;

    #pragma unroll
    for (int mt = 0; mt < 2; mt++)
        #pragma unroll
        for (int nt = 0; nt < 8; nt++)
            #pragma unroll
            for (int i = 0; i < 4; i++) acc[mt][nt][i] = 0.0f;

    const uint32 Ab0 = aBaseByte + (uint32)(mb + a_rl) * rowBytes;
    const uint32 Ab1 = Ab0 + 16u * rowBytes;
    const uint32 Bthread = (uint32)(nb + b_no + l7) * 128u;
    const bool bigA = (rowBytes == 512);

    for (int c = 0; c < kchunks; c++){
        if (c + 1 < kchunks){
            stage_chunk(smem_base, (c + 1 + s0) % 3, gimg, c + 1);
            cp_wait<1>();
        } else {
            cp_wait<PEND>();
        }
        __syncthreads();
        uint32 sBcur = smem_base + (SB_U + ((c + s0) % 3)*8192)*4;
        #pragma unroll
        for (int ks = 0; ks < 4; ks++){
            uint32 ar[2][4];
            int qA = (bigA ? c*8 : 0) + ks*2 + a_qo;
            uint32 axor = (uint32)((qA ^ l7) << 4);
            ldsm4(ar[0], Ab0 + axor);
            ldsm4(ar[1], Ab1 + axor);
            uint32 bxor = (uint32)((((ks*2 + b_kh) ^ b_r7)) << 4);
            #pragma unroll
            for (int j = 0; j < 4; j++){
                uint32 br[4];
                ldsm4(br, sBcur + Bthread + (uint32)(j*16*128) + bxor);
                #pragma unroll
                for (int mt = 0; mt < 2; mt++){
                    mma16(acc[mt][2*j],     ar[mt], br[0], br[1]);
                    mma16(acc[mt][2*j + 1], ar[mt], br[2], br[3]);
                }
            }
        }
        // no trailing sync: iter c+1 writes buf (c+2+s0)%3, whose last reads
        // (iter c-1) are ordered by the leading barrier of iter c.
    }
}

// epilogue: acc -> bf16 canonical (bias + relu), dst row stride 128 words
static __device__ __forceinline__ void epi_big(
    float acc[2][8][4], const float* __restrict__ gb, uint32* __restrict__ dstU)
{
    const int t = threadIdx.x;
    const int lane = t & 31, w = t >> 5;
    const int wm = w >> 2, wn = w & 3;
    const int mb = wm*32, nb = wn*64;
    const int g = lane >> 2, tig = lane & 3;
    #pragma unroll
    for (int mt = 0; mt < 2; mt++){
        int r0 = mb + mt*16 + g, r1 = r0 + 8;
        #pragma unroll
        for (int nt = 0; nt < 8; nt++){
            int col = nb + nt*8 + 2*tig;
            float b0 = gb[col], b1 = gb[col+1];
            uint32 w0 = bpack(fmaxf(acc[mt][nt][0] + b0, 0.0f), fmaxf(acc[mt][nt][1] + b1, 0.0f));
            uint32 w1 = bpack(fmaxf(acc[mt][nt][2] + b0, 0.0f), fmaxf(acc[mt][nt][3] + b1, 0.0f));
            int p = wn*32 + nt*4 + tig;
            int phys = (((p>>2) ^ (g & 7)) << 2) | (p & 3);
            dstU[r0*128 + phys] = w0;
            dstU[r1*128 + phys] = w1;
        }
    }
}

// ---------------- w2 GEMMs: warps 0..7, A = h1 at H1_OFF, B frags direct from L2 ----------------
static __device__ __forceinline__ void gemm_w2_n8(float acc8[4], uint32 smem_base, const uint32* __restrict__ wp){
    const int t = threadIdx.x;
    const int lane = t & 31, w = (t >> 5) & 7;
    const int l7 = lane & 7, lm = lane >> 3;
    const int a_rl = l7 + ((lm & 1) << 3);
    const int a_qo = lm >> 1;
    #pragma unroll
    for (int i = 0; i < 4; i++) acc8[i] = 0.0f;
    const uint32 Ab = smem_base + H1_OFF*4 + (uint32)(w*16 + a_rl)*512u;
    #pragma unroll
    for (int kc = 0; kc < 16; kc++){
        uint32 ar[4];
        int qA = kc*2 + a_qo;
        ldsm4(ar, Ab + (uint32)((qA ^ l7) << 4));
        mma16(acc8, ar, wp[(kc*2)*32 + lane], wp[(kc*2+1)*32 + lane]);
    }
}
static __device__ __forceinline__ void gemm_w2_n48(float acc48[6][4], uint32 smem_base, const uint32* __restrict__ wp){
    const int t = threadIdx.x;
    const int lane = t & 31, w = (t >> 5) & 7;
    const int l7 = lane & 7, lm = lane >> 3;
    const int a_rl = l7 + ((lm & 1) << 3);
    const int a_qo = lm >> 1;
    #pragma unroll
    for (int nt = 0; nt < 6; nt++)
        #pragma unroll
        for (int i = 0; i < 4; i++) acc48[nt][i] = 0.0f;
    const uint32 Ab = smem_base + H1_OFF*4 + (uint32)(w*16 + a_rl)*512u;
    #pragma unroll 4
    for (int kc = 0; kc < 16; kc++){
        uint32 ar[4];
        int qA = kc*2 + a_qo;
        ldsm4(ar, Ab + (uint32)((qA ^ l7) << 4));
        #pragma unroll
        for (int nt = 0; nt < 6; nt++)
            mma16(acc48[nt], ar, wp[((kc*6+nt)*2)*32 + lane], wp[((kc*6+nt)*2+1)*32 + lane]);
    }
}

// ---------------- phase A (proven) ----------------
static __device__ __forceinline__ void phaseA(
    int seg, const float* __restrict__ rays, const float* __restrict__ tim,
    const int* sidx, uint32* __restrict__ sF)
{
    const int t = threadIdx.x;
    const int pt = t >> 2, fg = t & 3;
    const int gi = sidx[pt];
    float px = rays[3*gi], py = rays[3*gi+1], pz = rays[3*gi+2];
    float tv = tim[gi];
    float cx = fminf(fmaxf((px*(1.0f/1.3f) + 1.0f)*0.5f, 0.0f), 1.0f) * 127.0f;
    float cy = fminf(fmaxf((py*(1.0f/1.3f) + 1.0f)*0.5f, 0.0f), 1.0f) * 127.0f;
    float cz = fminf(fmaxf((pz*(1.0f/1.3f) + 1.0f)*0.5f, 0.0f), 1.0f) * 127.0f;
    float tq = fminf(fmaxf(tv, 0.0f), 1.0f) * 63.0f;

    const uint32* sp = g_planes + (seg ? P_BG_SP : P_TGT_SP);
    const uint32* tp = g_planes + (seg ? P_BG_TP : P_TGT_TP);

    const uint32* PB[6];
    int O00[6], O10[6], O01[6], O11[6];
    float W00[6], W10[6], W01[6], W11[6];
#define SETP(s, bp, R2, uu, vv) { \
    float u_ = fminf(fmaxf((uu), 0.0f), 127.0f); \
    float v_ = fminf(fmaxf((vv), 0.0f), (float)((R2)-1)); \
    int i0 = (int)u_; int j0 = (int)v_; \
    int i1 = min(i0+1, 127); int j1 = min(j0+1, (R2)-1); \
    float fu = u_ - (float)i0, fv = v_ - (float)j0; \
    PB[s] = (bp); \
    O00[s] = (i0*(R2)+j0)*32; O10[s] = (i1*(R2)+j0)*32; \
    O01[s] = (i0*(R2)+j1)*32; O11[s] = (i1*(R2)+j1)*32; \
    W00[s] = (1.0f-fu)*(1.0f-fv); W10[s] = fu*(1.0f-fv); \
    W01[s] = (1.0f-fu)*fv;        W11[s] = fu*fv; }
    SETP(0, sp,          128, cx, cy)
    SETP(1, sp + 524288, 128, cx, cz)
    SETP(2, sp + 1048576,128, cy, cz)
    SETP(3, tp,           64, cx, tq)
    SETP(4, tp + 262144,  64, cy, tq)
    SETP(5, tp + 524288,  64, cz, tq)
#undef SETP
    #pragma unroll
    for (int h = 0; h < 2; h++){
        int foff = fg*8 + h*4;
        float r[8];
        #pragma unroll
        for (int j = 0; j < 8; j++) r[j] = 1.0f;
        #pragma unroll
        for (int s = 0; s < 6; s++){
            const uint32* bp = PB[s] + foff;
            uint4 u00 = *(const uint4*)(bp + O00[s]);
            uint4 u10 = *(const uint4*)(bp + O10[s]);
            uint4 u01 = *(const uint4*)(bp + O01[s]);
            uint4 u11 = *(const uint4*)(bp + O11[s]);
            const uint32* a0 = (const uint32*)&u00;
            const uint32* a1 = (const uint32*)&u10;
            const uint32* a2 = (const uint32*)&u01;
            const uint32* a3 = (const uint32*)&u11;
            #pragma unroll
            for (int wd = 0; wd < 4; wd++){
                float2 c00 = bf2f(a0[wd]);
                float2 c10 = bf2f(a1[wd]);
                float2 c01 = bf2f(a2[wd]);
                float2 c11 = bf2f(a3[wd]);
                r[2*wd]   *= c00.x*W00[s] + c10.x*W10[s] + c01.x*W01[s] + c11.x*W11[s];
                r[2*wd+1] *= c00.y*W00[s] + c10.y*W10[s] + c01.y*W01[s] + c11.y*W11[s];
            }
        }
        #pragma unroll
        for (int j = 0; j < 4; j++){
            int p = foff + j;
            int phys = (((p>>2) ^ (pt & 7)) << 2) | (p & 3);
            sF[pt*32 + phys] = bpack(r[2*j], r[2*j+1]);
        }
    }
}

// ---------------- main kernel (exact R10 structure) ----------------
__global__ void __launch_bounds__(512, 1) main_kernel(
    const float* __restrict__ rays, const float* __restrict__ rot_emb,
    const float* __restrict__ shs_emb, const float* __restrict__ tim,
    const float* __restrict__ st_b,   const float* __restrict__ bg_st_b,
    const float* __restrict__ pos_b1, const float* __restrict__ pos_b2,
    const float* __restrict__ bgpos_b1, const float* __restrict__ bgpos_b2,
    const float* __restrict__ rot_b1, const float* __restrict__ rot_b2,
    const float* __restrict__ shs_b1, const float* __restrict__ shs_b2,
    float* __restrict__ out, int n)
{
    extern __shared__ uint32 smu[];
    const uint32 smem_base = (uint32)__cvta_generic_to_shared(smu);
    __shared__ int sidx[128];
    __shared__ int s_meta[3];

    const int t = threadIdx.x;
    if (t == 0){
        int mc = g_cnt_m;
        int mtiles = (mc + 127) >> 7;
        int bid = blockIdx.x;
        int seg, start, cnt;
        if (bid < mtiles){ seg = 0; start = bid << 7; cnt = min(128, mc - start); }
        else {
            int uc = n - mc;
            start = (bid - mtiles) << 7;
            seg = 1;
            cnt = (start < uc) ? min(128, uc - start) : 0;
        }
        s_meta[0] = seg; s_meta[1] = cnt; s_meta[2] = start;
    }
    __syncthreads();
    const int cnt = s_meta[1];
    if (cnt <= 0) return;
    const int seg = s_meta[0], start = s_meta[2];
    if (t < 128){
        int j = (t < cnt) ? t : 0;
        sidx[t] = (seg == 0) ? g_idx[start + j] : g_idx[n - 1 - (start + j)];
    }
    __syncthreads();

    // prologue: stem chunk -> buf2
    stage_chunk(smem_base, 2, g_wimg + (seg ? IMG_BGST : IMG_ST), 0);

    phaseA(seg, rays, tim, sidx, smu + SF_U);

    // prefetch first head's chunk0 -> buf0 (in flight across the stem GEMM)
    const uint32* h0img = g_wimg + (seg ? IMG_BGPOSW1 : IMG_POSW1);
    stage_chunk(smem_base, 0, h0img, 0);

    float acc[2][8][4];

    // stem: A = feat (K=64), chunk in buf2; allow 1 pending group (head chunk0)
    gemm_big3<1>(acc, g_wimg, smem_base, smem_base + SF_U*4, 128, 1, 2);
    epi_big(acc, seg ? bg_st_b : st_b, smu + SA_U);
    __syncthreads();

    const int lane = t & 31, w = t >> 5;
    const int g = lane >> 2, tig = lane & 3;
    const int mb2 = (w & 7)*16;

    if (seg == 0){
        // ---- pos ----
        gemm_big3<0>(acc, g_wimg + IMG_POSW1, smem_base, smem_base + SA_U*4, 512, 4, 0);
        epi_big(acc, pos_b1, smu + H1_OFF);      // h1 -> bufs 1-2 (chunk3 sits in buf0)
        __syncthreads();
        if (w < 8){
            float a8[4];
            gemm_w2_n8(a8, smem_base, g_wimg + IMG_POSW2);
            #pragma unroll
            for (int i = 0; i < 2; i++){
                int gi = sidx[mb2 + g + 8*i];
                #pragma unroll
                for (int jj = 0; jj < 2; jj++){
                    int col = 2*tig + jj;
                    if (col < 3) out[(size_t)gi*3 + col] = rays[gi*3 + col] + a8[i*2+jj] + pos_b2[col];
                }
            }
        }
        stage_chunk(smem_base, 0, g_wimg + IMG_ROTW1, 0);   // buf0 free; h1 untouched
        __syncthreads();
        // ---- rot ----
        gemm_big3<0>(acc, g_wimg + IMG_ROTW1, smem_base, smem_base + SA_U*4, 512, 4, 0);
        epi_big(acc, rot_b1, smu + H1_OFF);
        __syncthreads();
        if (w < 8){
            float a8[4];
            gemm_w2_n8(a8, smem_base, g_wimg + IMG_ROTW2);
            #pragma unroll
            for (int i = 0; i < 2; i++){
                int gi = sidx[mb2 + g + 8*i];
                #pragma unroll
                for (int jj = 0; jj < 2; jj++){
                    int col = 2*tig + jj;
                    if (col < 4) out[(size_t)3*n + (size_t)gi*4 + col] = rot_emb[(size_t)gi*4 + col] + a8[i*2+jj] + rot_b2[col];
                }
            }
        }
        stage_chunk(smem_base, 0, g_wimg + IMG_SHSW1, 0);
        __syncthreads();
        // ---- shs ----
        gemm_big3<0>(acc, g_wimg + IMG_SHSW1, smem_base, smem_base + SA_U*4, 512, 4, 0);
        epi_big(acc, shs_b1, smu + H1_OFF);
        __syncthreads();
        if (w < 8){
            float a48[6][4];
            gemm_w2_n48(a48, smem_base, g_wimg + IMG_SHSW2);
            float* o8 = out + (size_t)8*n;
            #pragma unroll
            for (int i = 0; i < 2; i++){
                int gi = sidx[mb2 + g + 8*i];
                const float* se = shs_emb + (size_t)gi*48;
                float* od = o8 + (size_t)gi*48;
                #pragma unroll
                for (int nt = 0; nt < 6; nt++){
                    #pragma unroll
                    for (int jj = 0; jj < 2; jj++){
                        int col = nt*8 + 2*tig + jj;
                        od[col] = se[col] + a48[nt][i*2+jj] + shs_b2[col];
                    }
                }
            }
        }
    } else {
        // ---- bgpos ----
        gemm_big3<0>(acc, g_wimg + IMG_BGPOSW1, smem_base, smem_base + SA_U*4, 512, 4, 0);
        epi_big(acc, bgpos_b1, smu + H1_OFF);
        __syncthreads();
        if (w < 8){
            float a8[4];
            gemm_w2_n8(a8, smem_base, g_wimg + IMG_BGPOSW2);
            #pragma unroll
            for (int i = 0; i < 2; i++){
                int gi = sidx[mb2 + g + 8*i];
                #pragma unroll
                for (int jj = 0; jj < 2; jj++){
                    int col = 2*tig + jj;
                    if (col < 3) out[(size_t)gi*3 + col] = rays[gi*3 + col] + a8[i*2+jj] + bgpos_b2[col];
                }
            }
        }
    }
}

extern "C" void kernel_launch(void* const* d_in, const int* in_sizes, int n_in,
                              void* d_out, int out_size) {
    const float* rays    = (const float*)d_in[0];
    const float* rot_emb = (const float*)d_in[1];
    const float* shs_emb = (const float*)d_in[3];
    const float* tim     = (const float*)d_in[5];
    const float* h_emb   = (const float*)d_in[6];
    const void*  mask    = d_in[7];
    const float* tgt_sp  = (const float*)d_in[8];
    const float* tgt_tp  = (const float*)d_in[9];
    const float* bg_sp   = (const float*)d_in[10];
    const float* bg_tp   = (const float*)d_in[11];
    const float* st_w    = (const float*)d_in[12];
    const float* st_b    = (const float*)d_in[13];
    const float* bg_st_w = (const float*)d_in[14];
    const float* bg_st_b = (const float*)d_in[15];
    const float* pos_w1  = (const float*)d_in[16];
    const float* pos_b1  = (const float*)d_in[17];
    const float* pos_w2  = (const float*)d_in[18];
    const float* pos_b2  = (const float*)d_in[19];
    const float* bgpos_w1= (const float*)d_in[20];
    const float* bgpos_b1= (const float*)d_in[21];
    const float* bgpos_w2= (const float*)d_in[22];
    const float* bgpos_b2= (const float*)d_in[23];
    const float* rot_w1  = (const float*)d_in[24];
    const float* rot_b1  = (const float*)d_in[25];
    const float* rot_w2  = (const float*)d_in[26];
    const float* rot_b2  = (const float*)d_in[27];
    const float* shs_w1  = (const float*)d_in[28];
    const float* shs_b1  = (const float*)d_in[29];
    const float* shs_w2  = (const float*)d_in[30];
    const float* shs_b2  = (const float*)d_in[31];
    float* out = (float*)d_out;
    int n = in_sizes[0] / 3;

    cudaFuncSetAttribute(main_kernel, cudaFuncAttributeMaxDynamicSharedMemorySize, SMEM_BYTES);

    setup_kernel<<<1, 256>>>((const unsigned char*)mask);
    int eb = (n + 255)/256;
    prep_kernel<<<PB_BLKS + WB_BLKS + eb, 256>>>(
        tgt_sp, tgt_tp, bg_sp, bg_tp,
        st_w, bg_st_w, pos_w1, bgpos_w1, rot_w1, shs_w1,
        pos_w2, rot_w2, shs_w2, bgpos_w2,
        rot_emb, shs_emb, tim, h_emb, mask, out, n);
    int nb = (n + 127)/128 + 1;
    main_kernel<<<nb, 512, SMEM_BYTES>>>(
        rays, rot_emb, shs_emb, tim,
        st_b, bg_st_b,
        pos_b1, pos_b2, bgpos_b1, bgpos_b2,
        rot_b1, rot_b2, shs_b1, shs_b2,
        out, n);
}

// round 13
// speedup vs baseline: 1.4460x; 1.1028x over previous
#include <cuda_runtime.h>
#include <cuda_bf16.h>
#include <math.h>

#define NMAX 400000
typedef unsigned int uint32;

__device__ int g_cnt_m;
__device__ int g_cnt_u;
__device__ int g_mask_mode;
__device__ int g_idx[NMAX];

#define P_TGT_SP 0
#define P_TGT_TP 1572864
#define P_BG_SP  2359296
#define P_BG_TP  3932160
#define P_TOTAL  4718592
__device__ uint32 g_planes[P_TOTAL];

#define IMG_ST       0
#define IMG_BGST     8192
#define IMG_POSW1    16384
#define IMG_BGPOSW1  49152
#define IMG_ROTW1    81920
#define IMG_SHSW1    114688
#define IMG_POSW2    147456
#define IMG_ROTW2    148480
#define IMG_SHSW2    149504
#define IMG_BGPOSW2  155648
#define IMG_TOTAL    156672
__device__ uint32 g_wimg[IMG_TOTAL];

// ---------------- smem layout (u32 words) ----------------
#define SF_U   0          // feat: 128 x 32 words
#define SA_U   4096       // h: 128 x 128 words
#define H1_OFF 20480      // h1: 128 x 128 words
#define TOTAL_U 36864
#define SMEM_BYTES (TOTAL_U*4)

static __device__ __forceinline__ float sigm(float x){ return 1.0f/(1.0f+expf(-x)); }
static __device__ __forceinline__ uint32 bpack(float a, float b){
    __nv_bfloat162 h = __float22bfloat162_rn(make_float2(a,b));
    return *reinterpret_cast<uint32*>(&h);
}
static __device__ __forceinline__ float2 bf2f(uint32 w){
    __nv_bfloat162 h; *reinterpret_cast<uint32*>(&h) = w;
    return __bfloat1622float2(h);
}
static __device__ __forceinline__ void ldsm4(uint32* r, uint32 addr){
    asm volatile("ldmatrix.sync.aligned.m8n8.x4.shared.b16 {%0,%1,%2,%3},[%4];"
      : "=r"(r[0]),"=r"(r[1]),"=r"(r[2]),"=r"(r[3]) : "r"(addr));
}
static __device__ __forceinline__ void mma16(float* d, const uint32* a, uint32 b0, uint32 b1){
    asm volatile("mma.sync.aligned.m16n8k16.row.col.f32.bf16.bf16.f32 "
      "{%0,%1,%2,%3},{%4,%5,%6,%7},{%8,%9},{%0,%1,%2,%3};"
      : "+f"(d[0]),"+f"(d[1]),"+f"(d[2]),"+f"(d[3])
      : "r"(a[0]),"r"(a[1]),"r"(a[2]),"r"(a[3]),"r"(b0),"r"(b1));
}

// ---------------- setup: mask dtype sniff + counter reset ----------------
__global__ void setup_kernel(const unsigned char* __restrict__ mb){
    __shared__ int s3f, s3f1, s1off;
    if (threadIdx.x == 0){ s3f = 0; s3f1 = 0; s1off = 0; }
    __syncthreads();
    int a = 0, b = 0, c = 0;
    for (int i = threadIdx.x; i < 4096; i += blockDim.x){
        unsigned v = mb[i];
        if (v == 0x3fu){ a = 1; if ((i & 3) == 1) b = 1; }
        if (v == 0x01u && (i & 3) != 0) c = 1;
    }
    if (a) atomicOr(&s3f, 1);
    if (b) atomicOr(&s3f1, 1);
    if (c) atomicOr(&s1off, 1);
    __syncthreads();
    if (threadIdx.x == 0){
        g_mask_mode = s3f ? (s3f1 ? 3 : 2) : (s1off ? 0 : 1);
        g_cnt_m = 0; g_cnt_u = 0;
    }
}
static __device__ __forceinline__ bool read_mask(const void* m, int i, int mode){
    if (mode == 0) return ((const unsigned char*)m)[i] != 0;
    if (mode == 1) return ((const int*)m)[i] != 0;
    if (mode == 2) return ((const float*)m)[i] != 0.0f;
    return ((const unsigned short*)m)[i] != 0;
}

// ---------------- merged prep kernel: plane convert + weight convert + elem ----------------
#define PB_BLKS 18432            /* P_TOTAL / 256 */
#define WB_BLKS 612              /* ceil(IMG_TOTAL / 256) */
__global__ void prep_kernel(
    const float* __restrict__ tsp, const float* __restrict__ ttp,
    const float* __restrict__ bsp, const float* __restrict__ btp,
    const float* st_w, const float* bg_st_w,
    const float* pos_w1, const float* bgpos_w1, const float* rot_w1, const float* shs_w1,
    const float* pos_w2, const float* rot_w2, const float* shs_w2, const float* bgpos_w2,
    const float* __restrict__ rot_emb, const float* __restrict__ shs_emb,
    const float* __restrict__ tim, const float* __restrict__ h_emb,
    const void* __restrict__ mask, float* __restrict__ out, int n)
{
    int bid = blockIdx.x;
    if (bid < PB_BLKS){
        int i = bid*256 + threadIdx.x;
        const float* src; int off;
        if      (i < P_TGT_TP){ src = tsp; off = i; }
        else if (i < P_BG_SP) { src = ttp; off = i - P_TGT_TP; }
        else if (i < P_BG_TP) { src = bsp; off = i - P_BG_SP; }
        else                  { src = btp; off = i - P_BG_TP; }
        g_planes[i] = bpack(src[2*off], src[2*off+1]);
        return;
    }
    bid -= PB_BLKS;
    if (bid < WB_BLKS){
        int i = bid*256 + threadIdx.x;
        if (i >= IMG_TOTAL) return;
        if (i < IMG_POSW2){
            // W1 images in lane-vectorized fragment order:
            // word = (((kc*16 + ntp)*32 + lane)*4 + q)
            const float* src; int base;
            if      (i < IMG_BGST)   { src=st_w;    base=IMG_ST; }
            else if (i < IMG_POSW1)  { src=bg_st_w; base=IMG_BGST; }
            else if (i < IMG_BGPOSW1){ src=pos_w1;  base=IMG_POSW1; }
            else if (i < IMG_ROTW1)  { src=bgpos_w1;base=IMG_BGPOSW1; }
            else if (i < IMG_SHSW1)  { src=rot_w1;  base=IMG_ROTW1; }
            else                     { src=shs_w1;  base=IMG_SHSW1; }
            int wi = i - base;
            int q    = wi & 3;
            int lane = (wi >> 2) & 31;
            int ntp  = (wi >> 7) & 15;
            int kc   = wi >> 11;
            int nt = ntp*2 + (q >> 1);
            int h  = q & 1;
            int g  = lane >> 2, tig = lane & 3;
            int col = nt*8 + g;
            int k   = kc*16 + 2*tig + 8*h;
            g_wimg[i] = bpack(src[(size_t)k*256 + col], src[(size_t)(k+1)*256 + col]);
        } else {
            const float* src; int N, NT, base;
            if      (i < IMG_ROTW2)  { src=pos_w2;  N=3;  NT=1; base=IMG_POSW2; }
            else if (i < IMG_SHSW2)  { src=rot_w2;  N=4;  NT=1; base=IMG_ROTW2; }
            else if (i < IMG_BGPOSW2){ src=shs_w2;  N=48; NT=6; base=IMG_SHSW2; }
            else                     { src=bgpos_w2;N=3;  NT=1; base=IMG_BGPOSW2; }
            int wi = i - base;
            int lane = wi & 31;
            int tmp = wi >> 5;
            int h = tmp & 1;
            int tmp2 = tmp >> 1;
            int nt = tmp2 % NT;
            int kc = tmp2 / NT;
            int g = lane >> 2, tig = lane & 3;
            int k0 = kc*16 + 2*tig + 8*h;
            int col = nt*8 + g;
            float lo = 0.0f, hi = 0.0f;
            if (col < N){ lo = src[(size_t)k0*N + col]; hi = src[(size_t)(k0+1)*N + col]; }
            g_wimg[i] = bpack(lo, hi);
        }
        return;
    }
    bid -= WB_BLKS;
    // ---- elem ----
    __shared__ int sm_m, sm_u, base_m, base_u;
    if (threadIdx.x == 0){ sm_m = 0; sm_u = 0; }
    __syncthreads();
    int i = bid*256 + threadIdx.x;
    bool valid = (i < n);
    int mode = g_mask_mode;
    bool msk = false; int pos = 0;
    if (valid){
        msk = read_mask(mask, i, mode);
        pos = msk ? atomicAdd(&sm_m, 1) : atomicAdd(&sm_u, 1);
    }
    __syncthreads();
    if (threadIdx.x == 0){ base_m = atomicAdd(&g_cnt_m, sm_m); base_u = atomicAdd(&g_cnt_u, sm_u); }
    __syncthreads();
    if (!valid) return;
    float t0 = tim[0];
    float he0 = h_emb[3*i], he1 = h_emb[3*i+1], he2 = h_emb[3*i+2];
    float op;
    if (msk){ float mu = sigm(he2); float w = he1*he1; float d = t0 - mu; op = expf(-w*d*d); }
    else op = sigm(he0);
    out[(size_t)7*n + i] = op;
    if (msk){ g_idx[base_m + pos] = i; }
    else {
        g_idx[n - 1 - (base_u + pos)] = i;
        ((float4*)(out + (size_t)3*n))[i] = ((const float4*)rot_emb)[i];
        const float4* s4 = (const float4*)shs_emb + (size_t)i*12;
        float4* d4 = (float4*)(out + (size_t)8*n) + (size_t)i*12;
        #pragma unroll
        for (int q = 0; q < 12; q++) d4[q] = s4[q];
    }
}

// ---------------- big GEMM: B fragments direct from L2/L1 (no smem, no syncs) ----------------
template<int KK>
static __device__ __forceinline__ void gemm_fd(
    float acc[2][8][4], const uint32* __restrict__ img,
    uint32 aBaseByte, int rowBytes)
{
    const int t = threadIdx.x;
    const int lane = t & 31, w = t >> 5;
    const int wm = w >> 2, wn = w & 3;
    const int mb = wm*32;
    const int l7 = lane & 7, lm = lane >> 3;
    const int a_rl = l7 + ((lm & 1) << 3);
    const int a_qo = lm >> 1;

    #pragma unroll
    for (int mt = 0; mt < 2; mt++)
        #pragma unroll
        for (int nt = 0; nt < 8; nt++)
            #pragma unroll
            for (int i = 0; i < 4; i++) acc[mt][nt][i] = 0.0f;

    const uint32 Ab0 = aBaseByte + (uint32)(mb + a_rl) * rowBytes;
    const uint32 Ab1 = Ab0 + 16u * rowBytes;
    const uint4* wp4 = (const uint4*)img + (uint32)(wn*4)*32 + lane;

    #pragma unroll 4
    for (int kk = 0; kk < KK; kk++){
        uint32 ar[2][4];
        int qA = kk*2 + a_qo;
        uint32 axor = (uint32)((qA ^ l7) << 4);
        ldsm4(ar[0], Ab0 + axor);
        ldsm4(ar[1], Ab1 + axor);
        const uint4* wk = wp4 + (uint32)(kk*16)*32;
        #pragma unroll
        for (int j = 0; j < 4; j++){
            uint4 v = __ldg(wk + (uint32)j*32);
            #pragma unroll
            for (int mt = 0; mt < 2; mt++){
                mma16(acc[mt][2*j],     ar[mt], v.x, v.y);
                mma16(acc[mt][2*j + 1], ar[mt], v.z, v.w);
            }
        }
    }
}

// epilogue: acc -> bf16 canonical (bias + relu), dst row stride 128 words
static __device__ __forceinline__ void epi_big(
    float acc[2][8][4], const float* __restrict__ gb, uint32* __restrict__ dstU)
{
    const int t = threadIdx.x;
    const int lane = t & 31, w = t >> 5;
    const int wm = w >> 2, wn = w & 3;
    const int mb = wm*32, nb = wn*64;
    const int g = lane >> 2, tig = lane & 3;
    #pragma unroll
    for (int mt = 0; mt < 2; mt++){
        int r0 = mb + mt*16 + g, r1 = r0 + 8;
        #pragma unroll
        for (int nt = 0; nt < 8; nt++){
            int col = nb + nt*8 + 2*tig;
            float b0 = gb[col], b1 = gb[col+1];
            uint32 w0 = bpack(fmaxf(acc[mt][nt][0] + b0, 0.0f), fmaxf(acc[mt][nt][1] + b1, 0.0f));
            uint32 w1 = bpack(fmaxf(acc[mt][nt][2] + b0, 0.0f), fmaxf(acc[mt][nt][3] + b1, 0.0f));
            int p = wn*32 + nt*4 + tig;
            int phys = (((p>>2) ^ (g & 7)) << 2) | (p & 3);
            dstU[r0*128 + phys] = w0;
            dstU[r1*128 + phys] = w1;
        }
    }
}

// ---------------- w2 GEMMs: warps 0..7, A = h1 at H1_OFF, B frags direct from L2 ----------------
static __device__ __forceinline__ void gemm_w2_n8(float acc8[4], uint32 smem_base, const uint32* __restrict__ wp){
    const int t = threadIdx.x;
    const int lane = t & 31, w = (t >> 5) & 7;
    const int l7 = lane & 7, lm = lane >> 3;
    const int a_rl = l7 + ((lm & 1) << 3);
    const int a_qo = lm >> 1;
    #pragma unroll
    for (int i = 0; i < 4; i++) acc8[i] = 0.0f;
    const uint32 Ab = smem_base + H1_OFF*4 + (uint32)(w*16 + a_rl)*512u;
    #pragma unroll
    for (int kc = 0; kc < 16; kc++){
        uint32 ar[4];
        int qA = kc*2 + a_qo;
        ldsm4(ar, Ab + (uint32)((qA ^ l7) << 4));
        mma16(acc8, ar, wp[(kc*2)*32 + lane], wp[(kc*2+1)*32 + lane]);
    }
}
static __device__ __forceinline__ void gemm_w2_n48(float acc48[6][4], uint32 smem_base, const uint32* __restrict__ wp){
    const int t = threadIdx.x;
    const int lane = t & 31, w = (t >> 5) & 7;
    const int l7 = lane & 7, lm = lane >> 3;
    const int a_rl = l7 + ((lm & 1) << 3);
    const int a_qo = lm >> 1;
    #pragma unroll
    for (int nt = 0; nt < 6; nt++)
        #pragma unroll
        for (int i = 0; i < 4; i++) acc48[nt][i] = 0.0f;
    const uint32 Ab = smem_base + H1_OFF*4 + (uint32)(w*16 + a_rl)*512u;
    #pragma unroll 4
    for (int kc = 0; kc < 16; kc++){
        uint32 ar[4];
        int qA = kc*2 + a_qo;
        ldsm4(ar, Ab + (uint32)((qA ^ l7) << 4));
        #pragma unroll
        for (int nt = 0; nt < 6; nt++)
            mma16(acc48[nt], ar, wp[((kc*6+nt)*2)*32 + lane], wp[((kc*6+nt)*2+1)*32 + lane]);
    }
}

// ---------------- phase A (proven) ----------------
static __device__ __forceinline__ void phaseA(
    int seg, const float* __restrict__ rays, const float* __restrict__ tim,
    const int* sidx, uint32* __restrict__ sF)
{
    const int t = threadIdx.x;
    const int pt = t >> 2, fg = t & 3;
    const int gi = sidx[pt];
    float px = rays[3*gi], py = rays[3*gi+1], pz = rays[3*gi+2];
    float tv = tim[gi];
    float cx = fminf(fmaxf((px*(1.0f/1.3f) + 1.0f)*0.5f, 0.0f), 1.0f) * 127.0f;
    float cy = fminf(fmaxf((py*(1.0f/1.3f) + 1.0f)*0.5f, 0.0f), 1.0f) * 127.0f;
    float cz = fminf(fmaxf((pz*(1.0f/1.3f) + 1.0f)*0.5f, 0.0f), 1.0f) * 127.0f;
    float tq = fminf(fmaxf(tv, 0.0f), 1.0f) * 63.0f;

    const uint32* sp = g_planes + (seg ? P_BG_SP : P_TGT_SP);
    const uint32* tp = g_planes + (seg ? P_BG_TP : P_TGT_TP);

    const uint32* PB[6];
    int O00[6], O10[6], O01[6], O11[6];
    float W00[6], W10[6], W01[6], W11[6];
#define SETP(s, bp, R2, uu, vv) { \
    float u_ = fminf(fmaxf((uu), 0.0f), 127.0f); \
    float v_ = fminf(fmaxf((vv), 0.0f), (float)((R2)-1)); \
    int i0 = (int)u_; int j0 = (int)v_; \
    int i1 = min(i0+1, 127); int j1 = min(j0+1, (R2)-1); \
    float fu = u_ - (float)i0, fv = v_ - (float)j0; \
    PB[s] = (bp); \
    O00[s] = (i0*(R2)+j0)*32; O10[s] = (i1*(R2)+j0)*32; \
    O01[s] = (i0*(R2)+j1)*32; O11[s] = (i1*(R2)+j1)*32; \
    W00[s] = (1.0f-fu)*(1.0f-fv); W10[s] = fu*(1.0f-fv); \
    W01[s] = (1.0f-fu)*fv;        W11[s] = fu*fv; }
    SETP(0, sp,          128, cx, cy)
    SETP(1, sp + 524288, 128, cx, cz)
    SETP(2, sp + 1048576,128, cy, cz)
    SETP(3, tp,           64, cx, tq)
    SETP(4, tp + 262144,  64, cy, tq)
    SETP(5, tp + 524288,  64, cz, tq)
#undef SETP
    #pragma unroll
    for (int h = 0; h < 2; h++){
        int foff = fg*8 + h*4;
        float r[8];
        #pragma unroll
        for (int j = 0; j < 8; j++) r[j] = 1.0f;
        #pragma unroll
        for (int s = 0; s < 6; s++){
            const uint32* bp = PB[s] + foff;
            uint4 u00 = *(const uint4*)(bp + O00[s]);
            uint4 u10 = *(const uint4*)(bp + O10[s]);
            uint4 u01 = *(const uint4*)(bp + O01[s]);
            uint4 u11 = *(const uint4*)(bp + O11[s]);
            const uint32* a0 = (const uint32*)&u00;
            const uint32* a1 = (const uint32*)&u10;
            const uint32* a2 = (const uint32*)&u01;
            const uint32* a3 = (const uint32*)&u11;
            #pragma unroll
            for (int wd = 0; wd < 4; wd++){
                float2 c00 = bf2f(a0[wd]);
                float2 c10 = bf2f(a1[wd]);
                float2 c01 = bf2f(a2[wd]);
                float2 c11 = bf2f(a3[wd]);
                r[2*wd]   *= c00.x*W00[s] + c10.x*W10[s] + c01.x*W01[s] + c11.x*W11[s];
                r[2*wd+1] *= c00.y*W00[s] + c10.y*W10[s] + c01.y*W01[s] + c11.y*W11[s];
            }
        }
        #pragma unroll
        for (int j = 0; j < 4; j++){
            int p = foff + j;
            int phys = (((p>>2) ^ (pt & 7)) << 2) | (p & 3);
            sF[pt*32 + phys] = bpack(r[2*j], r[2*j+1]);
        }
    }
}

// ---------------- main kernel ----------------
__global__ void __launch_bounds__(512, 1) main_kernel(
    const float* __restrict__ rays, const float* __restrict__ rot_emb,
    const float* __restrict__ shs_emb, const float* __restrict__ tim,
    const float* __restrict__ st_b,   const float* __restrict__ bg_st_b,
    const float* __restrict__ pos_b1, const float* __restrict__ pos_b2,
    const float* __restrict__ bgpos_b1, const float* __restrict__ bgpos_b2,
    const float* __restrict__ rot_b1, const float* __restrict__ rot_b2,
    const float* __restrict__ shs_b1, const float* __restrict__ shs_b2,
    float* __restrict__ out, int n)
{
    extern __shared__ uint32 smu[];
    const uint32 smem_base = (uint32)__cvta_generic_to_shared(smu);
    __shared__ int sidx[128];
    __shared__ int s_meta[3];

    const int t = threadIdx.x;
    if (t == 0){
        int mc = g_cnt_m;
        int mtiles = (mc + 127) >> 7;
        int bid = blockIdx.x;
        int seg, start, cnt;
        if (bid < mtiles){ seg = 0; start = bid << 7; cnt = min(128, mc - start); }
        else {
            int uc = n - mc;
            start = (bid - mtiles) << 7;
            seg = 1;
            cnt = (start < uc) ? min(128, uc - start) : 0;
        }
        s_meta[0] = seg; s_meta[1] = cnt; s_meta[2] = start;
    }
    __syncthreads();
    const int cnt = s_meta[1];
    if (cnt <= 0) return;
    const int seg = s_meta[0], start = s_meta[2];
    if (t < 128){
        int j = (t < cnt) ? t : 0;
        sidx[t] = (seg == 0) ? g_idx[start + j] : g_idx[n - 1 - (start + j)];
    }
    __syncthreads();

    phaseA(seg, rays, tim, sidx, smu + SF_U);
    __syncthreads();

    float acc[2][8][4];
    const uint32 sFByte = smem_base + SF_U*4;
    const uint32 sAByte = smem_base + SA_U*4;

    // stem: A = feat (K=64), B direct from L2
    gemm_fd<4>(acc, g_wimg + (seg ? IMG_BGST : IMG_ST), sFByte, 128);
    epi_big(acc, seg ? bg_st_b : st_b, smu + SA_U);
    __syncthreads();

    const int lane = t & 31, w = t >> 5;
    const int g = lane >> 2, tig = lane & 3;
    const int mb2 = (w & 7)*16;

    if (seg == 0){
        // ---- pos ----
        gemm_fd<16>(acc, g_wimg + IMG_POSW1, sAByte, 512);
        epi_big(acc, pos_b1, smu + H1_OFF);
        __syncthreads();
        if (w < 8){
            float a8[4];
            gemm_w2_n8(a8, smem_base, g_wimg + IMG_POSW2);
            #pragma unroll
            for (int i = 0; i < 2; i++){
                int gi = sidx[mb2 + g + 8*i];
                #pragma unroll
                for (int jj = 0; jj < 2; jj++){
                    int col = 2*tig + jj;
                    if (col < 3) out[(size_t)gi*3 + col] = rays[gi*3 + col] + a8[i*2+jj] + pos_b2[col];
                }
            }
        }
        __syncthreads();
        // ---- rot ----
        gemm_fd<16>(acc, g_wimg + IMG_ROTW1, sAByte, 512);
        epi_big(acc, rot_b1, smu + H1_OFF);
        __syncthreads();
        if (w < 8){
            float a8[4];
            gemm_w2_n8(a8, smem_base, g_wimg + IMG_ROTW2);
            #pragma unroll
            for (int i = 0; i < 2; i++){
                int gi = sidx[mb2 + g + 8*i];
                #pragma unroll
                for (int jj = 0; jj < 2; jj++){
                    int col = 2*tig + jj;
                    if (col < 4) out[(size_t)3*n + (size_t)gi*4 + col] = rot_emb[(size_t)gi*4 + col] + a8[i*2+jj] + rot_b2[col];
                }
            }
        }
        __syncthreads();
        // ---- shs ----
        gemm_fd<16>(acc, g_wimg + IMG_SHSW1, sAByte, 512);
        epi_big(acc, shs_b1, smu + H1_OFF);
        __syncthreads();
        if (w < 8){
            float a48[6][4];
            gemm_w2_n48(a48, smem_base, g_wimg + IMG_SHSW2);
            float* o8 = out + (size_t)8*n;
            #pragma unroll
            for (int i = 0; i < 2; i++){
                int gi = sidx[mb2 + g + 8*i];
                const float* se = shs_emb + (size_t)gi*48;
                float* od = o8 + (size_t)gi*48;
                #pragma unroll
                for (int nt = 0; nt < 6; nt++){
                    #pragma unroll
                    for (int jj = 0; jj < 2; jj++){
                        int col = nt*8 + 2*tig + jj;
                        od[col] = se[col] + a48[nt][i*2+jj] + shs_b2[col];
                    }
                }
            }
        }
    } else {
        // ---- bgpos ----
        gemm_fd<16>(acc, g_wimg + IMG_BGPOSW1, sAByte, 512);
        epi_big(acc, bgpos_b1, smu + H1_OFF);
        __syncthreads();
        if (w < 8){
            float a8[4];
            gemm_w2_n8(a8, smem_base, g_wimg + IMG_BGPOSW2);
            #pragma unroll
            for (int i = 0; i < 2; i++){
                int gi = sidx[mb2 + g + 8*i];
                #pragma unroll
                for (int jj = 0; jj < 2; jj++){
                    int col = 2*tig + jj;
                    if (col < 3) out[(size_t)gi*3 + col] = rays[gi*3 + col] + a8[i*2+jj] + bgpos_b2[col];
                }
            }
        }
    }
}

extern "C" void kernel_launch(void* const* d_in, const int* in_sizes, int n_in,
                              void* d_out, int out_size) {
    const float* rays    = (const float*)d_in[0];
    const float* rot_emb = (const float*)d_in[1];
    const float* shs_emb = (const float*)d_in[3];
    const float* tim     = (const float*)d_in[5];
    const float* h_emb   = (const float*)d_in[6];
    const void*  mask    = d_in[7];
    const float* tgt_sp  = (const float*)d_in[8];
    const float* tgt_tp  = (const float*)d_in[9];
    const float* bg_sp   = (const float*)d_in[10];
    const float* bg_tp   = (const float*)d_in[11];
    const float* st_w    = (const float*)d_in[12];
    const float* st_b    = (const float*)d_in[13];
    const float* bg_st_w = (const float*)d_in[14];
    const float* bg_st_b = (const float*)d_in[15];
    const float* pos_w1  = (const float*)d_in[16];
    const float* pos_b1  = (const float*)d_in[17];
    const float* pos_w2  = (const float*)d_in[18];
    const float* pos_b2  = (const float*)d_in[19];
    const float* bgpos_w1= (const float*)d_in[20];
    const float* bgpos_b1= (const float*)d_in[21];
    const float* bgpos_w2= (const float*)d_in[22];
    const float* bgpos_b2= (const float*)d_in[23];
    const float* rot_w1  = (const float*)d_in[24];
    const float* rot_b1  = (const float*)d_in[25];
    const float* rot_w2  = (const float*)d_in[26];
    const float* rot_b2  = (const float*)d_in[27];
    const float* shs_w1  = (const float*)d_in[28];
    const float* shs_b1  = (const float*)d_in[29];
    const float* shs_w2  = (const float*)d_in[30];
    const float* shs_b2  = (const float*)d_in[31];
    float* out = (float*)d_out;
    int n = in_sizes[0] / 3;

    cudaFuncSetAttribute(main_kernel, cudaFuncAttributeMaxDynamicSharedMemorySize, SMEM_BYTES);

    setup_kernel<<<1, 256>>>((const unsigned char*)mask);
    int eb = (n + 255)/256;
    prep_kernel<<<PB_BLKS + WB_BLKS + eb, 256>>>(
        tgt_sp, tgt_tp, bg_sp, bg_tp,
        st_w, bg_st_w, pos_w1, bgpos_w1, rot_w1, shs_w1,
        pos_w2, rot_w2, shs_w2, bgpos_w2,
        rot_emb, shs_emb, tim, h_emb, mask, out, n);
    int nb = (n + 127)/128 + 1;
    main_kernel<<<nb, 512, SMEM_BYTES>>>(
        rays, rot_emb, shs_emb, tim,
        st_b, bg_st_b,
        pos_b1, pos_b2, bgpos_b1, bgpos_b2,
        rot_b1, rot_b2, shs_b1, shs_b2,
        out, n);
}

// round 14
// speedup vs baseline: 1.4708x; 1.0172x over previous
#include <cuda_runtime.h>
#include <cuda_bf16.h>
#include <math.h>

#define NMAX 400000
typedef unsigned int uint32;

__device__ int g_cnt_m;
__device__ int g_cnt_u;
__device__ int g_mask_mode;
__device__ int g_idx[NMAX];

#define P_TGT_SP 0
#define P_TGT_TP 1572864
#define P_BG_SP  2359296
#define P_BG_TP  3932160
#define P_TOTAL  4718592
__device__ uint32 g_planes[P_TOTAL];

#define IMG_ST       0
#define IMG_BGST     8192
#define IMG_POSW1    16384
#define IMG_BGPOSW1  49152
#define IMG_ROTW1    81920
#define IMG_SHSW1    114688
#define IMG_POSW2    147456
#define IMG_ROTW2    148480
#define IMG_SHSW2    149504
#define IMG_BGPOSW2  155648
#define IMG_TOTAL    156672
__device__ uint32 g_wimg[IMG_TOTAL];

// ---------------- smem layout (u32 words) ----------------
#define SF_U   0          // feat: 128 x 32 words
#define SA_U   4096       // h: 128 x 128 words
#define H1_OFF 20480      // h1: 128 x 128 words
#define TOTAL_U 36864
#define SMEM_BYTES (TOTAL_U*4)

static __device__ __forceinline__ float sigm(float x){ return 1.0f/(1.0f+expf(-x)); }
static __device__ __forceinline__ uint32 bpack(float a, float b){
    __nv_bfloat162 h = __float22bfloat162_rn(make_float2(a,b));
    return *reinterpret_cast<uint32*>(&h);
}
static __device__ __forceinline__ float2 bf2f(uint32 w){
    __nv_bfloat162 h; *reinterpret_cast<uint32*>(&h) = w;
    return __bfloat1622float2(h);
}
static __device__ __forceinline__ void ldsm4(uint32* r, uint32 addr){
    asm volatile("ldmatrix.sync.aligned.m8n8.x4.shared.b16 {%0,%1,%2,%3},[%4];"
      : "=r"(r[0]),"=r"(r[1]),"=r"(r[2]),"=r"(r[3]) : "r"(addr));
}
static __device__ __forceinline__ void mma16(float* d, const uint32* a, uint32 b0, uint32 b1){
    asm volatile("mma.sync.aligned.m16n8k16.row.col.f32.bf16.bf16.f32 "
      "{%0,%1,%2,%3},{%4,%5,%6,%7},{%8,%9},{%0,%1,%2,%3};"
      : "+f"(d[0]),"+f"(d[1]),"+f"(d[2]),"+f"(d[3])
      : "r"(a[0]),"r"(a[1]),"r"(a[2]),"r"(a[3]),"r"(b0),"r"(b1));
}

// ---------------- setup: mask dtype sniff + counter reset ----------------
__global__ void setup_kernel(const unsigned char* __restrict__ mb){
    __shared__ int s3f, s3f1, s1off;
    if (threadIdx.x == 0){ s3f = 0; s3f1 = 0; s1off = 0; }
    __syncthreads();
    int a = 0, b = 0, c = 0;
    for (int i = threadIdx.x; i < 4096; i += blockDim.x){
        unsigned v = mb[i];
        if (v == 0x3fu){ a = 1; if ((i & 3) == 1) b = 1; }
        if (v == 0x01u && (i & 3) != 0) c = 1;
    }
    if (a) atomicOr(&s3f, 1);
    if (b) atomicOr(&s3f1, 1);
    if (c) atomicOr(&s1off, 1);
    __syncthreads();
    if (threadIdx.x == 0){
        g_mask_mode = s3f ? (s3f1 ? 3 : 2) : (s1off ? 0 : 1);
        g_cnt_m = 0; g_cnt_u = 0;
    }
}
static __device__ __forceinline__ bool read_mask(const void* m, int i, int mode){
    if (mode == 0) return ((const unsigned char*)m)[i] != 0;
    if (mode == 1) return ((const int*)m)[i] != 0;
    if (mode == 2) return ((const float*)m)[i] != 0.0f;
    return ((const unsigned short*)m)[i] != 0;
}

// ---------------- merged prep kernel: plane convert + weight convert + elem ----------------
#define PB_BLKS 18432            /* P_TOTAL / 256 */
#define WB_BLKS 612              /* ceil(IMG_TOTAL / 256) */
__global__ void prep_kernel(
    const float* __restrict__ tsp, const float* __restrict__ ttp,
    const float* __restrict__ bsp, const float* __restrict__ btp,
    const float* st_w, const float* bg_st_w,
    const float* pos_w1, const float* bgpos_w1, const float* rot_w1, const float* shs_w1,
    const float* pos_w2, const float* rot_w2, const float* shs_w2, const float* bgpos_w2,
    const float* __restrict__ rot_emb, const float* __restrict__ shs_emb,
    const float* __restrict__ tim, const float* __restrict__ h_emb,
    const void* __restrict__ mask, float* __restrict__ out, int n)
{
    int bid = blockIdx.x;
    if (bid < PB_BLKS){
        int i = bid*256 + threadIdx.x;
        const float* src; int off;
        if      (i < P_TGT_TP){ src = tsp; off = i; }
        else if (i < P_BG_SP) { src = ttp; off = i - P_TGT_TP; }
        else if (i < P_BG_TP) { src = bsp; off = i - P_BG_SP; }
        else                  { src = btp; off = i - P_BG_TP; }
        g_planes[i] = bpack(src[2*off], src[2*off+1]);
        return;
    }
    bid -= PB_BLKS;
    if (bid < WB_BLKS){
        int i = bid*256 + threadIdx.x;
        if (i >= IMG_TOTAL) return;
        if (i < IMG_POSW2){
            // W1 images, lane-vectorized fragment order:
            // word = (((kc*16 + ntp)*32 + lane)*4 + q)
            const float* src; int base;
            if      (i < IMG_BGST)   { src=st_w;    base=IMG_ST; }
            else if (i < IMG_POSW1)  { src=bg_st_w; base=IMG_BGST; }
            else if (i < IMG_BGPOSW1){ src=pos_w1;  base=IMG_POSW1; }
            else if (i < IMG_ROTW1)  { src=bgpos_w1;base=IMG_BGPOSW1; }
            else if (i < IMG_SHSW1)  { src=rot_w1;  base=IMG_ROTW1; }
            else                     { src=shs_w1;  base=IMG_SHSW1; }
            int wi = i - base;
            int q    = wi & 3;
            int lane = (wi >> 2) & 31;
            int ntp  = (wi >> 7) & 15;
            int kc   = wi >> 11;
            int nt = ntp*2 + (q >> 1);
            int h  = q & 1;
            int g  = lane >> 2, tig = lane & 3;
            int col = nt*8 + g;
            int k   = kc*16 + 2*tig + 8*h;
            g_wimg[i] = bpack(src[(size_t)k*256 + col], src[(size_t)(k+1)*256 + col]);
        } else {
            // w2 frag images, uint2-vectorized: word = ((kc*NT + nt)*32 + lane)*2 + h
            const float* src; int N, NT, base;
            if      (i < IMG_ROTW2)  { src=pos_w2;  N=3;  NT=1; base=IMG_POSW2; }
            else if (i < IMG_SHSW2)  { src=rot_w2;  N=4;  NT=1; base=IMG_ROTW2; }
            else if (i < IMG_BGPOSW2){ src=shs_w2;  N=48; NT=6; base=IMG_SHSW2; }
            else                     { src=bgpos_w2;N=3;  NT=1; base=IMG_BGPOSW2; }
            int wi = i - base;
            int h = wi & 1;
            int lane = (wi >> 1) & 31;
            int tmp = wi >> 6;
            int nt = tmp % NT;
            int kc = tmp / NT;
            int g = lane >> 2, tig = lane & 3;
            int k0 = kc*16 + 2*tig + 8*h;
            int col = nt*8 + g;
            float lo = 0.0f, hi = 0.0f;
            if (col < N){ lo = src[(size_t)k0*N + col]; hi = src[(size_t)(k0+1)*N + col]; }
            g_wimg[i] = bpack(lo, hi);
        }
        return;
    }
    bid -= WB_BLKS;
    // ---- elem ----
    __shared__ int sm_m, sm_u, base_m, base_u;
    if (threadIdx.x == 0){ sm_m = 0; sm_u = 0; }
    __syncthreads();
    int i = bid*256 + threadIdx.x;
    bool valid = (i < n);
    int mode = g_mask_mode;
    bool msk = false; int pos = 0;
    if (valid){
        msk = read_mask(mask, i, mode);
        pos = msk ? atomicAdd(&sm_m, 1) : atomicAdd(&sm_u, 1);
    }
    __syncthreads();
    if (threadIdx.x == 0){ base_m = atomicAdd(&g_cnt_m, sm_m); base_u = atomicAdd(&g_cnt_u, sm_u); }
    __syncthreads();
    if (!valid) return;
    float t0 = tim[0];
    float he0 = h_emb[3*i], he1 = h_emb[3*i+1], he2 = h_emb[3*i+2];
    float op;
    if (msk){ float mu = sigm(he2); float w = he1*he1; float d = t0 - mu; op = expf(-w*d*d); }
    else op = sigm(he0);
    out[(size_t)7*n + i] = op;
    if (msk){ g_idx[base_m + pos] = i; }
    else {
        g_idx[n - 1 - (base_u + pos)] = i;
        ((float4*)(out + (size_t)3*n))[i] = ((const float4*)rot_emb)[i];
        const float4* s4 = (const float4*)shs_emb + (size_t)i*12;
        float4* d4 = (float4*)(out + (size_t)8*n) + (size_t)i*12;
        #pragma unroll
        for (int q = 0; q < 12; q++) d4[q] = s4[q];
    }
}

// ---------------- big GEMM: B fragments direct from L2/L1, batched loads ----------------
template<int KK>
static __device__ __forceinline__ void gemm_fd(
    float acc[2][8][4], const uint32* __restrict__ img,
    uint32 aBaseByte, int rowBytes)
{
    const int t = threadIdx.x;
    const int lane = t & 31, w = t >> 5;
    const int wm = w >> 2, wn = w & 3;
    const int mb = wm*32;
    const int l7 = lane & 7, lm = lane >> 3;
    const int a_rl = l7 + ((lm & 1) << 3);
    const int a_qo = lm >> 1;

    #pragma unroll
    for (int mt = 0; mt < 2; mt++)
        #pragma unroll
        for (int nt = 0; nt < 8; nt++)
            #pragma unroll
            for (int i = 0; i < 4; i++) acc[mt][nt][i] = 0.0f;

    const uint32 Ab0 = aBaseByte + (uint32)(mb + a_rl) * rowBytes;
    const uint32 Ab1 = Ab0 + 16u * rowBytes;
    const uint4* wp4 = (const uint4*)img + (uint32)(wn*4)*32 + lane;

    #pragma unroll 4
    for (int kk = 0; kk < KK; kk++){
        uint32 ar[2][4];
        int qA = kk*2 + a_qo;
        uint32 axor = (uint32)((qA ^ l7) << 4);
        ldsm4(ar[0], Ab0 + axor);
        ldsm4(ar[1], Ab1 + axor);
        const uint4* wk = wp4 + (uint32)(kk*16)*32;
        uint4 v0 = __ldg(wk);
        uint4 v1 = __ldg(wk + 32);
        uint4 v2 = __ldg(wk + 64);
        uint4 v3 = __ldg(wk + 96);
        #pragma unroll
        for (int mt = 0; mt < 2; mt++){
            mma16(acc[mt][0], ar[mt], v0.x, v0.y);
            mma16(acc[mt][1], ar[mt], v0.z, v0.w);
            mma16(acc[mt][2], ar[mt], v1.x, v1.y);
            mma16(acc[mt][3], ar[mt], v1.z, v1.w);
            mma16(acc[mt][4], ar[mt], v2.x, v2.y);
            mma16(acc[mt][5], ar[mt], v2.z, v2.w);
            mma16(acc[mt][6], ar[mt], v3.x, v3.y);
            mma16(acc[mt][7], ar[mt], v3.z, v3.w);
        }
    }
}

// epilogue: acc -> bf16 canonical (bias + relu), dst row stride 128 words
static __device__ __forceinline__ void epi_big(
    float acc[2][8][4], const float* __restrict__ gb, uint32* __restrict__ dstU)
{
    const int t = threadIdx.x;
    const int lane = t & 31, w = t >> 5;
    const int wm = w >> 2, wn = w & 3;
    const int mb = wm*32, nb = wn*64;
    const int g = lane >> 2, tig = lane & 3;
    #pragma unroll
    for (int mt = 0; mt < 2; mt++){
        int r0 = mb + mt*16 + g, r1 = r0 + 8;
        #pragma unroll
        for (int nt = 0; nt < 8; nt++){
            int col = nb + nt*8 + 2*tig;
            float b0 = gb[col], b1 = gb[col+1];
            uint32 w0 = bpack(fmaxf(acc[mt][nt][0] + b0, 0.0f), fmaxf(acc[mt][nt][1] + b1, 0.0f));
            uint32 w1 = bpack(fmaxf(acc[mt][nt][2] + b0, 0.0f), fmaxf(acc[mt][nt][3] + b1, 0.0f));
            int p = wn*32 + nt*4 + tig;
            int phys = (((p>>2) ^ (g & 7)) << 2) | (p & 3);
            dstU[r0*128 + phys] = w0;
            dstU[r1*128 + phys] = w1;
        }
    }
}

// ---------------- w2 GEMMs: warps 0..7, A = h1 at H1_OFF, B uint2 frags direct from L2 ----------------
static __device__ __forceinline__ void gemm_w2_n8(float acc8[4], uint32 smem_base, const uint32* __restrict__ wp){
    const int t = threadIdx.x;
    const int lane = t & 31, w = (t >> 5) & 7;
    const int l7 = lane & 7, lm = lane >> 3;
    const int a_rl = l7 + ((lm & 1) << 3);
    const int a_qo = lm >> 1;
    #pragma unroll
    for (int i = 0; i < 4; i++) acc8[i] = 0.0f;
    const uint32 Ab = smem_base + H1_OFF*4 + (uint32)(w*16 + a_rl)*512u;
    const uint2* wp2 = (const uint2*)wp + lane;
    #pragma unroll
    for (int kc = 0; kc < 16; kc++){
        uint32 ar[4];
        int qA = kc*2 + a_qo;
        ldsm4(ar, Ab + (uint32)((qA ^ l7) << 4));
        uint2 v = __ldg(wp2 + kc*32);
        mma16(acc8, ar, v.x, v.y);
    }
}
static __device__ __forceinline__ void gemm_w2_n48(float acc48[6][4], uint32 smem_base, const uint32* __restrict__ wp){
    const int t = threadIdx.x;
    const int lane = t & 31, w = (t >> 5) & 7;
    const int l7 = lane & 7, lm = lane >> 3;
    const int a_rl = l7 + ((lm & 1) << 3);
    const int a_qo = lm >> 1;
    #pragma unroll
    for (int nt = 0; nt < 6; nt++)
        #pragma unroll
        for (int i = 0; i < 4; i++) acc48[nt][i] = 0.0f;
    const uint32 Ab = smem_base + H1_OFF*4 + (uint32)(w*16 + a_rl)*512u;
    const uint2* wp2 = (const uint2*)wp + lane;
    #pragma unroll 4
    for (int kc = 0; kc < 16; kc++){
        uint32 ar[4];
        int qA = kc*2 + a_qo;
        ldsm4(ar, Ab + (uint32)((qA ^ l7) << 4));
        #pragma unroll
        for (int nt = 0; nt < 6; nt++){
            uint2 v = __ldg(wp2 + (kc*6 + nt)*32);
            mma16(acc48[nt], ar, v.x, v.y);
        }
    }
}

// ---------------- phase A (proven) ----------------
static __device__ __forceinline__ void phaseA(
    int seg, const float* __restrict__ rays, const float* __restrict__ tim,
    const int* sidx, uint32* __restrict__ sF)
{
    const int t = threadIdx.x;
    const int pt = t >> 2, fg = t & 3;
    const int gi = sidx[pt];
    float px = rays[3*gi], py = rays[3*gi+1], pz = rays[3*gi+2];
    float tv = tim[gi];
    float cx = fminf(fmaxf((px*(1.0f/1.3f) + 1.0f)*0.5f, 0.0f), 1.0f) * 127.0f;
    float cy = fminf(fmaxf((py*(1.0f/1.3f) + 1.0f)*0.5f, 0.0f), 1.0f) * 127.0f;
    float cz = fminf(fmaxf((pz*(1.0f/1.3f) + 1.0f)*0.5f, 0.0f), 1.0f) * 127.0f;
    float tq = fminf(fmaxf(tv, 0.0f), 1.0f) * 63.0f;

    const uint32* sp = g_planes + (seg ? P_BG_SP : P_TGT_SP);
    const uint32* tp = g_planes + (seg ? P_BG_TP : P_TGT_TP);

    const uint32* PB[6];
    int O00[6], O10[6], O01[6], O11[6];
    float W00[6], W10[6], W01[6], W11[6];
#define SETP(s, bp, R2, uu, vv) { \
    float u_ = fminf(fmaxf((uu), 0.0f), 127.0f); \
    float v_ = fminf(fmaxf((vv), 0.0f), (float)((R2)-1)); \
    int i0 = (int)u_; int j0 = (int)v_; \
    int i1 = min(i0+1, 127); int j1 = min(j0+1, (R2)-1); \
    float fu = u_ - (float)i0, fv = v_ - (float)j0; \
    PB[s] = (bp); \
    O00[s] = (i0*(R2)+j0)*32; O10[s] = (i1*(R2)+j0)*32; \
    O01[s] = (i0*(R2)+j1)*32; O11[s] = (i1*(R2)+j1)*32; \
    W00[s] = (1.0f-fu)*(1.0f-fv); W10[s] = fu*(1.0f-fv); \
    W01[s] = (1.0f-fu)*fv;        W11[s] = fu*fv; }
    SETP(0, sp,          128, cx, cy)
    SETP(1, sp + 524288, 128, cx, cz)
    SETP(2, sp + 1048576,128, cy, cz)
    SETP(3, tp,           64, cx, tq)
    SETP(4, tp + 262144,  64, cy, tq)
    SETP(5, tp + 524288,  64, cz, tq)
#undef SETP
    #pragma unroll
    for (int h = 0; h < 2; h++){
        int foff = fg*8 + h*4;
        float r[8];
        #pragma unroll
        for (int j = 0; j < 8; j++) r[j] = 1.0f;
        #pragma unroll
        for (int s = 0; s < 6; s++){
            const uint32* bp = PB[s] + foff;
            uint4 u00 = *(const uint4*)(bp + O00[s]);
            uint4 u10 = *(const uint4*)(bp + O10[s]);
            uint4 u01 = *(const uint4*)(bp + O01[s]);
            uint4 u11 = *(const uint4*)(bp + O11[s]);
            const uint32* a0 = (const uint32*)&u00;
            const uint32* a1 = (const uint32*)&u10;
            const uint32* a2 = (const uint32*)&u01;
            const uint32* a3 = (const uint32*)&u11;
            #pragma unroll
            for (int wd = 0; wd < 4; wd++){
                float2 c00 = bf2f(a0[wd]);
                float2 c10 = bf2f(a1[wd]);
                float2 c01 = bf2f(a2[wd]);
                float2 c11 = bf2f(a3[wd]);
                r[2*wd]   *= c00.x*W00[s] + c10.x*W10[s] + c01.x*W01[s] + c11.x*W11[s];
                r[2*wd+1] *= c00.y*W00[s] + c10.y*W10[s] + c01.y*W01[s] + c11.y*W11[s];
            }
        }
        #pragma unroll
        for (int j = 0; j < 4; j++){
            int p = foff + j;
            int phys = (((p>>2) ^ (pt & 7)) << 2) | (p & 3);
            sF[pt*32 + phys] = bpack(r[2*j], r[2*j+1]);
        }
    }
}

// ---------------- main kernel ----------------
__global__ void __launch_bounds__(512, 1) main_kernel(
    const float* __restrict__ rays, const float* __restrict__ rot_emb,
    const float* __restrict__ shs_emb, const float* __restrict__ tim,
    const float* __restrict__ st_b,   const float* __restrict__ bg_st_b,
    const float* __restrict__ pos_b1, const float* __restrict__ pos_b2,
    const float* __restrict__ bgpos_b1, const float* __restrict__ bgpos_b2,
    const float* __restrict__ rot_b1, const float* __restrict__ rot_b2,
    const float* __restrict__ shs_b1, const float* __restrict__ shs_b2,
    float* __restrict__ out, int n)
{
    extern __shared__ uint32 smu[];
    const uint32 smem_base = (uint32)__cvta_generic_to_shared(smu);
    __shared__ int sidx[128];
    __shared__ int s_meta[3];

    const int t = threadIdx.x;
    if (t == 0){
        int mc = g_cnt_m;
        int mtiles = (mc + 127) >> 7;
        int bid = blockIdx.x;
        int seg, start, cnt;
        if (bid < mtiles){ seg = 0; start = bid << 7; cnt = min(128, mc - start); }
        else {
            int uc = n - mc;
            start = (bid - mtiles) << 7;
            seg = 1;
            cnt = (start < uc) ? min(128, uc - start) : 0;
        }
        s_meta[0] = seg; s_meta[1] = cnt; s_meta[2] = start;
    }
    __syncthreads();
    const int cnt = s_meta[1];
    if (cnt <= 0) return;
    const int seg = s_meta[0], start = s_meta[2];
    if (t < 128){
        int j = (t < cnt) ? t : 0;
        sidx[t] = (seg == 0) ? g_idx[start + j] : g_idx[n - 1 - (start + j)];
    }
    __syncthreads();

    phaseA(seg, rays, tim, sidx, smu + SF_U);
    __syncthreads();

    float acc[2][8][4];
    const uint32 sFByte = smem_base + SF_U*4;
    const uint32 sAByte = smem_base + SA_U*4;

    // stem: A = feat (K=64), B direct from L2
    gemm_fd<4>(acc, g_wimg + (seg ? IMG_BGST : IMG_ST), sFByte, 128);
    epi_big(acc, seg ? bg_st_b : st_b, smu + SA_U);
    __syncthreads();

    const int lane = t & 31, w = t >> 5;
    const int g = lane >> 2, tig = lane & 3;
    const int mb2 = (w & 7)*16;

    if (seg == 0){
        // ---- pos ----
        gemm_fd<16>(acc, g_wimg + IMG_POSW1, sAByte, 512);
        epi_big(acc, pos_b1, smu + H1_OFF);
        __syncthreads();
        if (w < 8){
            float a8[4];
            gemm_w2_n8(a8, smem_base, g_wimg + IMG_POSW2);
            #pragma unroll
            for (int i = 0; i < 2; i++){
                int gi = sidx[mb2 + g + 8*i];
                #pragma unroll
                for (int jj = 0; jj < 2; jj++){
                    int col = 2*tig + jj;
                    if (col < 3) out[(size_t)gi*3 + col] = rays[gi*3 + col] + a8[i*2+jj] + pos_b2[col];
                }
            }
        }
        __syncthreads();
        // ---- rot ----
        gemm_fd<16>(acc, g_wimg + IMG_ROTW1, sAByte, 512);
        epi_big(acc, rot_b1, smu + H1_OFF);
        __syncthreads();
        if (w < 8){
            float a8[4];
            gemm_w2_n8(a8, smem_base, g_wimg + IMG_ROTW2);
            #pragma unroll
            for (int i = 0; i < 2; i++){
                int gi = sidx[mb2 + g + 8*i];
                #pragma unroll
                for (int jj = 0; jj < 2; jj++){
                    int col = 2*tig + jj;
                    if (col < 4) out[(size_t)3*n + (size_t)gi*4 + col] = rot_emb[(size_t)gi*4 + col] + a8[i*2+jj] + rot_b2[col];
                }
            }
        }
        __syncthreads();
        // ---- shs ----
        gemm_fd<16>(acc, g_wimg + IMG_SHSW1, sAByte, 512);
        epi_big(acc, shs_b1, smu + H1_OFF);
        __syncthreads();
        if (w < 8){
            float a48[6][4];
            gemm_w2_n48(a48, smem_base, g_wimg + IMG_SHSW2);
            float* o8 = out + (size_t)8*n;
            #pragma unroll
            for (int i = 0; i < 2; i++){
                int gi = sidx[mb2 + g + 8*i];
                const float* se = shs_emb + (size_t)gi*48;
                float* od = o8 + (size_t)gi*48;
                #pragma unroll
                for (int nt = 0; nt < 6; nt++){
                    #pragma unroll
                    for (int jj = 0; jj < 2; jj++){
                        int col = nt*8 + 2*tig + jj;
                        od[col] = se[col] + a48[nt][i*2+jj] + shs_b2[col];
                    }
                }
            }
        }
    } else {
        // ---- bgpos ----
        gemm_fd<16>(acc, g_wimg + IMG_BGPOSW1, sAByte, 512);
        epi_big(acc, bgpos_b1, smu + H1_OFF);
        __syncthreads();
        if (w < 8){
            float a8[4];
            gemm_w2_n8(a8, smem_base, g_wimg + IMG_BGPOSW2);
            #pragma unroll
            for (int i = 0; i < 2; i++){
                int gi = sidx[mb2 + g + 8*i];
                #pragma unroll
                for (int jj = 0; jj < 2; jj++){
                    int col = 2*tig + jj;
                    if (col < 3) out[(size_t)gi*3 + col] = rays[gi*3 + col] + a8[i*2+jj] + bgpos_b2[col];
                }
            }
        }
    }
}

extern "C" void kernel_launch(void* const* d_in, const int* in_sizes, int n_in,
                              void* d_out, int out_size) {
    const float* rays    = (const float*)d_in[0];
    const float* rot_emb = (const float*)d_in[1];
    const float* shs_emb = (const float*)d_in[3];
    const float* tim     = (const float*)d_in[5];
    const float* h_emb   = (const float*)d_in[6];
    const void*  mask    = d_in[7];
    const float* tgt_sp  = (const float*)d_in[8];
    const float* tgt_tp  = (const float*)d_in[9];
    const float* bg_sp   = (const float*)d_in[10];
    const float* bg_tp   = (const float*)d_in[11];
    const float* st_w    = (const float*)d_in[12];
    const float* st_b    = (const float*)d_in[13];
    const float* bg_st_w = (const float*)d_in[14];
    const float* bg_st_b = (const float*)d_in[15];
    const float* pos_w1  = (const float*)d_in[16];
    const float* pos_b1  = (const float*)d_in[17];
    const float* pos_w2  = (const float*)d_in[18];
    const float* pos_b2  = (const float*)d_in[19];
    const float* bgpos_w1= (const float*)d_in[20];
    const float* bgpos_b1= (const float*)d_in[21];
    const float* bgpos_w2= (const float*)d_in[22];
    const float* bgpos_b2= (const float*)d_in[23];
    const float* rot_w1  = (const float*)d_in[24];
    const float* rot_b1  = (const float*)d_in[25];
    const float* rot_w2  = (const float*)d_in[26];
    const float* rot_b2  = (const float*)d_in[27];
    const float* shs_w1  = (const float*)d_in[28];
    const float* shs_b1  = (const float*)d_in[29];
    const float* shs_w2  = (const float*)d_in[30];
    const float* shs_b2  = (const float*)d_in[31];
    float* out = (float*)d_out;
    int n = in_sizes[0] / 3;

    cudaFuncSetAttribute(main_kernel, cudaFuncAttributeMaxDynamicSharedMemorySize, SMEM_BYTES);

    setup_kernel<<<1, 256>>>((const unsigned char*)mask);
    int eb = (n + 255)/256;
    prep_kernel<<<PB_BLKS + WB_BLKS + eb, 256>>>(
        tgt_sp, tgt_tp, bg_sp, bg_tp,
        st_w, bg_st_w, pos_w1, bgpos_w1, rot_w1, shs_w1,
        pos_w2, rot_w2, shs_w2, bgpos_w2,
        rot_emb, shs_emb, tim, h_emb, mask, out, n);
    int nb = (n + 127)/128 + 1;
    main_kernel<<<nb, 512, SMEM_BYTES>>>(
        rays, rot_emb, shs_emb, tim,
        st_b, bg_st_b,
        pos_b1, pos_b2, bgpos_b1, bgpos_b2,
        rot_b1, rot_b2, shs_b1, shs_b2,
        out, n);
}